// round 1
// baseline (speedup 1.0000x reference)
#include <cuda_runtime.h>

#define N_NODES 50000
#define N_EDGES 400000
#define D_IN    256
#define D_HID   512
#define D_OUT   128
#define N_LAYERS 4

// Scratch (allocation-free rule: __device__ globals)
__device__ float g_h [(size_t)N_NODES * D_HID];   // 102.4 MB
__device__ float g_hw[(size_t)N_NODES * D_HID];   // 102.4 MB
__device__ float g_deg [N_NODES];
__device__ float g_dinv[N_NODES];

// ---------------------------------------------------------------------------
// degree / normalization
// ---------------------------------------------------------------------------
__global__ void deg_init_kernel(float* __restrict__ deg) {
    int n = blockIdx.x * blockDim.x + threadIdx.x;
    if (n < N_NODES) deg[n] = 1.0f;   // self-loop
}

__global__ void deg_accum_kernel(const int* __restrict__ dst, float* __restrict__ deg) {
    int e = blockIdx.x * blockDim.x + threadIdx.x;
    if (e < N_EDGES) atomicAdd(&deg[dst[e]], 1.0f);
}

__global__ void dinv_kernel(const float* __restrict__ deg, float* __restrict__ dinv) {
    int n = blockIdx.x * blockDim.x + threadIdx.x;
    if (n < N_NODES) dinv[n] = rsqrtf(deg[n]);    // deg >= 1 always
}

// ---------------------------------------------------------------------------
// Tiled fp32 GEMM: C[M,N] = A[M,K] @ B[K,N] (+bias) (+relu)
// BM=128, BN=64, BK=16, TM=8, TN=4, 256 threads
// ---------------------------------------------------------------------------
template<bool RELU, bool BIAS>
__launch_bounds__(256)
__global__ void gemm_kernel(const float* __restrict__ A, const float* __restrict__ B,
                            const float* __restrict__ bias, float* __restrict__ C,
                            int M, int K, int N) {
    constexpr int BM = 128, BN = 64, BK = 16, TM = 8, TN = 4;
    __shared__ float As[BK][BM];
    __shared__ float Bs[BK][BN];

    const int tid = threadIdx.x;
    const int tx  = tid % (BN / TN);   // 0..15 (col groups)
    const int ty  = tid / (BN / TN);   // 0..15 (row groups)
    const int row0 = blockIdx.x * BM;
    const int col0 = blockIdx.y * BN;

    float acc[TM][TN];
    #pragma unroll
    for (int i = 0; i < TM; i++)
        #pragma unroll
        for (int j = 0; j < TN; j++) acc[i][j] = 0.0f;

    for (int k0 = 0; k0 < K; k0 += BK) {
        // A tile (BM x BK), stored transposed As[k][row]
        #pragma unroll
        for (int i = tid; i < BM * BK; i += 256) {
            int r = i / BK, k = i % BK;
            int gr = row0 + r;
            As[k][r] = (gr < M) ? A[(size_t)gr * K + k0 + k] : 0.0f;
        }
        // B tile (BK x BN)
        #pragma unroll
        for (int i = tid; i < BK * BN; i += 256) {
            int k = i / BN, c = i % BN;
            Bs[k][c] = B[(size_t)(k0 + k) * N + col0 + c];
        }
        __syncthreads();

        #pragma unroll
        for (int k = 0; k < BK; k++) {
            float a[TM], b[TN];
            #pragma unroll
            for (int i = 0; i < TM; i++) a[i] = As[k][ty * TM + i];
            #pragma unroll
            for (int j = 0; j < TN; j++) b[j] = Bs[k][tx * TN + j];
            #pragma unroll
            for (int i = 0; i < TM; i++)
                #pragma unroll
                for (int j = 0; j < TN; j++)
                    acc[i][j] = fmaf(a[i], b[j], acc[i][j]);
        }
        __syncthreads();
    }

    #pragma unroll
    for (int i = 0; i < TM; i++) {
        int gr = row0 + ty * TM + i;
        if (gr >= M) continue;
        #pragma unroll
        for (int j = 0; j < TN; j++) {
            int gc = col0 + tx * TN + j;
            float v = acc[i][j];
            if (BIAS) v += bias[gc];
            if (RELU) v = fmaxf(v, 0.0f);
            C[(size_t)gr * N + gc] = v;
        }
    }
}

// ---------------------------------------------------------------------------
// self-loop + bias init: h[n,c] = dinv[n]^2 * hw[n,c] + bc[c]
// one float4 per thread
// ---------------------------------------------------------------------------
__global__ void selfloop_bias_kernel(const float* __restrict__ hw,
                                     const float* __restrict__ dinv,
                                     const float* __restrict__ bc,
                                     float* __restrict__ out) {
    const long long total = (long long)N_NODES * (D_HID / 4);
    long long idx = (long long)blockIdx.x * blockDim.x + threadIdx.x;
    if (idx >= total) return;
    int n  = (int)(idx / (D_HID / 4));
    int c4 = (int)(idx % (D_HID / 4));
    float di = dinv[n];
    float nm = di * di;
    float4 v = reinterpret_cast<const float4*>(hw)[idx];
    float4 b = reinterpret_cast<const float4*>(bc)[c4];
    float4 o;
    o.x = fmaf(v.x, nm, b.x);
    o.y = fmaf(v.y, nm, b.y);
    o.z = fmaf(v.z, nm, b.z);
    o.w = fmaf(v.w, nm, b.w);
    reinterpret_cast<float4*>(out)[idx] = o;
}

// ---------------------------------------------------------------------------
// edge scatter: out[dst] += dinv[src]*dinv[dst] * hw[src]
// 128 threads (float4 lanes) per edge; vector reduction atomics
// ---------------------------------------------------------------------------
__global__ void scatter_kernel(const float* __restrict__ hw,
                               const int* __restrict__ src,
                               const int* __restrict__ dst,
                               const float* __restrict__ dinv,
                               float* __restrict__ out) {
    long long idx = (long long)blockIdx.x * blockDim.x + threadIdx.x;
    int e = (int)(idx >> 7);
    if (e >= N_EDGES) return;
    int lane = (int)(idx & 127);
    int s = src[e], d = dst[e];
    float nm = dinv[s] * dinv[d];
    float4 v = reinterpret_cast<const float4*>(hw + (size_t)s * D_HID)[lane];
    v.x *= nm; v.y *= nm; v.z *= nm; v.w *= nm;
    float* addr = out + (size_t)d * D_HID + lane * 4;
    asm volatile("red.global.add.v4.f32 [%0], {%1,%2,%3,%4};"
                 :: "l"(addr), "f"(v.x), "f"(v.y), "f"(v.z), "f"(v.w)
                 : "memory");
}

// ---------------------------------------------------------------------------
extern "C" void kernel_launch(void* const* d_in, const int* in_sizes, int n_in,
                              void* d_out, int out_size) {
    const float* x  = (const float*)d_in[0];
    const int*   ei = (const int*)  d_in[1];   // [2, E]
    const float* W1 = (const float*)d_in[2];
    const float* b1 = (const float*)d_in[3];
    const float* Wc = (const float*)d_in[4];   // [L, 512, 512]
    const float* bc = (const float*)d_in[5];   // [L, 512]
    const float* W2 = (const float*)d_in[6];
    const float* b2 = (const float*)d_in[7];
    float* out = (float*)d_out;

    float *h, *hw, *deg, *dinv;
    cudaGetSymbolAddress((void**)&h,    g_h);
    cudaGetSymbolAddress((void**)&hw,   g_hw);
    cudaGetSymbolAddress((void**)&deg,  g_deg);
    cudaGetSymbolAddress((void**)&dinv, g_dinv);

    const int* src = ei;
    const int* dst = ei + N_EDGES;

    deg_init_kernel <<<(N_NODES + 255) / 256, 256>>>(deg);
    deg_accum_kernel<<<(N_EDGES + 255) / 256, 256>>>(dst, deg);
    dinv_kernel     <<<(N_NODES + 255) / 256, 256>>>(deg, dinv);

    dim3 g1((N_NODES + 127) / 128, D_HID / 64);
    gemm_kernel<true, true><<<g1, 256>>>(x, W1, b1, h, N_NODES, D_IN, D_HID);

    const int sl_blocks = (int)(((long long)N_NODES * (D_HID / 4) + 255) / 256);
    const int sc_blocks = (int)(((long long)N_EDGES * 128 + 255) / 256);

    for (int l = 0; l < N_LAYERS; l++) {
        gemm_kernel<false, false><<<g1, 256>>>(h, Wc + (size_t)l * D_HID * D_HID,
                                               nullptr, hw, N_NODES, D_HID, D_HID);
        selfloop_bias_kernel<<<sl_blocks, 256>>>(hw, dinv, bc + (size_t)l * D_HID, h);
        scatter_kernel<<<sc_blocks, 256>>>(hw, src, dst, dinv, h);
    }

    dim3 g2((N_NODES + 127) / 128, D_OUT / 64);
    gemm_kernel<false, true><<<g2, 256>>>(h, W2, b2, out, N_NODES, D_HID, D_OUT);
}

// round 2
// speedup vs baseline: 1.4991x; 1.4991x over previous
#include <cuda_runtime.h>

#define N_NODES 50000
#define N_EDGES 400000
#define D_IN    256
#define D_HID   512
#define D_OUT   128
#define N_LAYERS 4

// Scratch (allocation-free rule: __device__ globals)
__device__ float g_h0[(size_t)N_NODES * D_HID];   // 102.4 MB
__device__ float g_h1[(size_t)N_NODES * D_HID];   // 102.4 MB
__device__ float g_hw[(size_t)N_NODES * D_HID];   // 102.4 MB
__device__ float g_deg [N_NODES];
__device__ float g_dinv[N_NODES];

// ---------------------------------------------------------------------------
// degree / normalization
// ---------------------------------------------------------------------------
__global__ void deg_init_kernel(float* __restrict__ deg) {
    int n = blockIdx.x * blockDim.x + threadIdx.x;
    if (n < N_NODES) deg[n] = 1.0f;   // self-loop
}

__global__ void deg_accum_kernel(const int* __restrict__ dst, float* __restrict__ deg) {
    int e = blockIdx.x * blockDim.x + threadIdx.x;
    if (e < N_EDGES) atomicAdd(&deg[dst[e]], 1.0f);
}

__global__ void dinv_kernel(const float* __restrict__ deg, float* __restrict__ dinv) {
    int n = blockIdx.x * blockDim.x + threadIdx.x;
    if (n < N_NODES) dinv[n] = rsqrtf(deg[n]);    // deg >= 1 always
}

// ---------------------------------------------------------------------------
// Tiled fp32 GEMM: C[M,N] = A[M,K] @ B[K,N]
// BM=128, BN=128, BK=16, TM=8, TN=8, 256 threads, all-float4 smem access.
// GCN epilogue additionally writes D = dinv[row]^2 * C + bias (self-loop term).
// ---------------------------------------------------------------------------
template<bool RELU, bool BIAS, bool GCN>
__launch_bounds__(256)
__global__ void gemm128_kernel(const float* __restrict__ A, const float* __restrict__ B,
                               const float* __restrict__ bias, float* __restrict__ C,
                               float* __restrict__ D, const float* __restrict__ dinv,
                               int M, int K, int N) {
    constexpr int BM = 128, BN = 128, BK = 16;
    __shared__ __align__(16) float As[BK][BM + 4];
    __shared__ __align__(16) float Bs[BK][BN];

    const int tid = threadIdx.x;
    const int tx  = tid & 15;    // 0..15 -> 8 cols each
    const int ty  = tid >> 4;    // 0..15 -> 8 rows each
    const int row0 = blockIdx.x * BM;
    const int col0 = blockIdx.y * BN;

    float acc[8][8];
    #pragma unroll
    for (int i = 0; i < 8; i++)
        #pragma unroll
        for (int j = 0; j < 8; j++) acc[i][j] = 0.0f;

    for (int k0 = 0; k0 < K; k0 += BK) {
        // A tile: 128 rows x 16 k  = 512 float4 loads, stored transposed
        #pragma unroll
        for (int f = tid; f < 512; f += 256) {
            int r  = f >> 2;
            int kq = f & 3;
            int gr = row0 + r;
            float4 v = make_float4(0.f, 0.f, 0.f, 0.f);
            if (gr < M) v = *reinterpret_cast<const float4*>(&A[(size_t)gr * K + k0 + kq * 4]);
            As[kq * 4 + 0][r] = v.x;
            As[kq * 4 + 1][r] = v.y;
            As[kq * 4 + 2][r] = v.z;
            As[kq * 4 + 3][r] = v.w;
        }
        // B tile: 16 k x 128 cols = 512 float4 loads, direct
        #pragma unroll
        for (int f = tid; f < 512; f += 256) {
            int k  = f >> 5;
            int cq = f & 31;
            *reinterpret_cast<float4*>(&Bs[k][cq * 4]) =
                *reinterpret_cast<const float4*>(&B[(size_t)(k0 + k) * N + col0 + cq * 4]);
        }
        __syncthreads();

        #pragma unroll
        for (int k = 0; k < BK; k++) {
            float4 a0 = *reinterpret_cast<const float4*>(&As[k][ty * 8]);
            float4 a1 = *reinterpret_cast<const float4*>(&As[k][ty * 8 + 4]);
            float4 b0 = *reinterpret_cast<const float4*>(&Bs[k][tx * 8]);
            float4 b1 = *reinterpret_cast<const float4*>(&Bs[k][tx * 8 + 4]);
            float a[8] = {a0.x, a0.y, a0.z, a0.w, a1.x, a1.y, a1.z, a1.w};
            float b[8] = {b0.x, b0.y, b0.z, b0.w, b1.x, b1.y, b1.z, b1.w};
            #pragma unroll
            for (int i = 0; i < 8; i++)
                #pragma unroll
                for (int j = 0; j < 8; j++)
                    acc[i][j] = fmaf(a[i], b[j], acc[i][j]);
        }
        __syncthreads();
    }

    // epilogue
    #pragma unroll
    for (int i = 0; i < 8; i++) {
        int gr = row0 + ty * 8 + i;
        if (gr >= M) continue;
        float nm = 0.0f;
        if (GCN) { float di = dinv[gr]; nm = di * di; }
        #pragma unroll
        for (int jq = 0; jq < 2; jq++) {
            int gc = col0 + tx * 8 + jq * 4;
            float4 v = make_float4(acc[i][jq * 4 + 0], acc[i][jq * 4 + 1],
                                   acc[i][jq * 4 + 2], acc[i][jq * 4 + 3]);
            if (BIAS) {
                float4 bb = *reinterpret_cast<const float4*>(&bias[gc]);
                v.x += bb.x; v.y += bb.y; v.z += bb.z; v.w += bb.w;
            }
            if (RELU) {
                v.x = fmaxf(v.x, 0.f); v.y = fmaxf(v.y, 0.f);
                v.z = fmaxf(v.z, 0.f); v.w = fmaxf(v.w, 0.f);
            }
            *reinterpret_cast<float4*>(&C[(size_t)gr * N + gc]) = v;
            if (GCN) {
                float4 bb = *reinterpret_cast<const float4*>(&bias[gc]);
                float4 w;
                w.x = fmaf(v.x, nm, bb.x);
                w.y = fmaf(v.y, nm, bb.y);
                w.z = fmaf(v.z, nm, bb.z);
                w.w = fmaf(v.w, nm, bb.w);
                *reinterpret_cast<float4*>(&D[(size_t)gr * N + gc]) = w;
            }
        }
    }
}

// ---------------------------------------------------------------------------
// edge scatter: out[dst] += dinv[src]*dinv[dst] * hw[src]
// 128 threads (float4 lanes) per edge; vector reduction atomics
// ---------------------------------------------------------------------------
__global__ void scatter_kernel(const float* __restrict__ hw,
                               const int* __restrict__ src,
                               const int* __restrict__ dst,
                               const float* __restrict__ dinv,
                               float* __restrict__ out) {
    long long idx = (long long)blockIdx.x * blockDim.x + threadIdx.x;
    int e = (int)(idx >> 7);
    if (e >= N_EDGES) return;
    int lane = (int)(idx & 127);
    int s = __ldg(&src[e]), d = __ldg(&dst[e]);
    float nm = __ldg(&dinv[s]) * __ldg(&dinv[d]);
    float4 v = reinterpret_cast<const float4*>(hw + (size_t)s * D_HID)[lane];
    v.x *= nm; v.y *= nm; v.z *= nm; v.w *= nm;
    float* addr = out + (size_t)d * D_HID + lane * 4;
    asm volatile("red.global.add.v4.f32 [%0], {%1,%2,%3,%4};"
                 :: "l"(addr), "f"(v.x), "f"(v.y), "f"(v.z), "f"(v.w)
                 : "memory");
}

// ---------------------------------------------------------------------------
extern "C" void kernel_launch(void* const* d_in, const int* in_sizes, int n_in,
                              void* d_out, int out_size) {
    const float* x  = (const float*)d_in[0];
    const int*   ei = (const int*)  d_in[1];   // [2, E]
    const float* W1 = (const float*)d_in[2];
    const float* b1 = (const float*)d_in[3];
    const float* Wc = (const float*)d_in[4];   // [L, 512, 512]
    const float* bc = (const float*)d_in[5];   // [L, 512]
    const float* W2 = (const float*)d_in[6];
    const float* b2 = (const float*)d_in[7];
    float* out = (float*)d_out;

    float *h0, *h1, *hw, *deg, *dinv;
    cudaGetSymbolAddress((void**)&h0,   g_h0);
    cudaGetSymbolAddress((void**)&h1,   g_h1);
    cudaGetSymbolAddress((void**)&hw,   g_hw);
    cudaGetSymbolAddress((void**)&deg,  g_deg);
    cudaGetSymbolAddress((void**)&dinv, g_dinv);

    const int* src = ei;
    const int* dst = ei + N_EDGES;

    deg_init_kernel <<<(N_NODES + 255) / 256, 256>>>(deg);
    deg_accum_kernel<<<(N_EDGES + 255) / 256, 256>>>(dst, deg);
    dinv_kernel     <<<(N_NODES + 255) / 256, 256>>>(deg, dinv);

    // dnn1: x @ W1 + b1, ReLU  -> h0
    dim3 g1((N_NODES + 127) / 128, D_HID / 128);
    gemm128_kernel<true, true, false><<<g1, 256>>>(x, W1, b1, h0, nullptr, nullptr,
                                                   N_NODES, D_IN, D_HID);

    const int sc_blocks = (int)(((long long)N_EDGES * 128 + 255) / 256);

    float* hc = h0;
    float* hn = h1;
    for (int l = 0; l < N_LAYERS; l++) {
        // hw = hc @ Wc[l];  hn = dinv^2 * hw + bc[l]  (self-loop + bias, fused)
        gemm128_kernel<false, false, true><<<g1, 256>>>(hc, Wc + (size_t)l * D_HID * D_HID,
                                                        bc + (size_t)l * D_HID, hw, hn, dinv,
                                                        N_NODES, D_HID, D_HID);
        // hn += scatter(norm * hw[src])
        scatter_kernel<<<sc_blocks, 256>>>(hw, src, dst, dinv, hn);
        float* t = hc; hc = hn; hn = t;
    }

    // dnn2: hc @ W2 + b2 -> out
    dim3 g2((N_NODES + 127) / 128, D_OUT / 128);
    gemm128_kernel<false, true, false><<<g2, 256>>>(hc, W2, b2, out, nullptr, nullptr,
                                                    N_NODES, D_HID, D_OUT);
}

// round 5
// speedup vs baseline: 2.5388x; 1.6936x over previous
#include <cuda_runtime.h>
#include <cuda_bf16.h>
#include <cstdint>

#define N_NODES 50000
#define N_EDGES 400000
#define D_IN    256
#define D_HID   512
#define D_OUT   128
#define N_LAYERS 4

// ---------------------------------------------------------------------------
// Scratch (__device__ globals; allocation-free rule)
// ---------------------------------------------------------------------------
__device__ float g_h0[(size_t)N_NODES * D_HID];
__device__ float g_h1[(size_t)N_NODES * D_HID];
__device__ float g_hw[(size_t)N_NODES * D_HID];
__device__ float g_deg [N_NODES];
__device__ float g_dinv[N_NODES];
__device__ __align__(16) __nv_bfloat16 g_ahi[(size_t)N_NODES * D_HID];
__device__ __align__(16) __nv_bfloat16 g_alo[(size_t)N_NODES * D_HID];
// transposed weights, bf16 hi/lo: W1T[512,256] | WcT[4][512,512] | W2T[128,512]
#define W1T_OFF 0
#define WCT_OFF (D_HID * D_IN)
#define W2T_OFF (WCT_OFF + N_LAYERS * D_HID * D_HID)
#define W_TOTAL (W2T_OFF + D_OUT * D_HID)
__device__ __align__(16) __nv_bfloat16 g_whi[W_TOTAL];
__device__ __align__(16) __nv_bfloat16 g_wlo[W_TOTAL];

// ---------------------------------------------------------------------------
static __device__ __forceinline__ uint32_t smem_u32(const void* p) {
    uint32_t a;
    asm("{ .reg .u64 t; cvta.to.shared.u64 t, %1; cvt.u32.u64 %0, t; }" : "=r"(a) : "l"(p));
    return a;
}

#define CP_ASYNC16(dst, src) \
    asm volatile("cp.async.cg.shared.global [%0], [%1], 16;" :: "r"(dst), "l"(src) : "memory")
#define CP_COMMIT() asm volatile("cp.async.commit_group;" ::: "memory")
#define CP_WAIT1()  asm volatile("cp.async.wait_group 1;"  ::: "memory")

#define LDMATRIX_X4(r0, r1, r2, r3, addr) \
    asm volatile("ldmatrix.sync.aligned.m8n8.x4.shared.b16 {%0,%1,%2,%3}, [%4];" \
                 : "=r"(r0), "=r"(r1), "=r"(r2), "=r"(r3) : "r"(addr))

#define MMA16816(c0, c1, c2, c3, a0, a1, a2, a3, b0, b1) \
    asm volatile("mma.sync.aligned.m16n8k16.row.col.f32.bf16.bf16.f32 " \
                 "{%0,%1,%2,%3}, {%4,%5,%6,%7}, {%8,%9}, {%0,%1,%2,%3};" \
                 : "+f"(c0), "+f"(c1), "+f"(c2), "+f"(c3) \
                 : "r"(a0), "r"(a1), "r"(a2), "r"(a3), "r"(b0), "r"(b1))

// ---------------------------------------------------------------------------
// degree / normalization
// ---------------------------------------------------------------------------
__global__ void deg_init_kernel(float* __restrict__ deg) {
    int n = blockIdx.x * blockDim.x + threadIdx.x;
    if (n < N_NODES) deg[n] = 1.0f;
}
__global__ void deg_accum_kernel(const int* __restrict__ dst, float* __restrict__ deg) {
    int e = blockIdx.x * blockDim.x + threadIdx.x;
    if (e < N_EDGES) atomicAdd(&deg[dst[e]], 1.0f);
}
__global__ void dinv_kernel(const float* __restrict__ deg, float* __restrict__ dinv) {
    int n = blockIdx.x * blockDim.x + threadIdx.x;
    if (n < N_NODES) dinv[n] = rsqrtf(deg[n]);
}

// ---------------------------------------------------------------------------
// fp32 -> bf16 hi/lo split
// ---------------------------------------------------------------------------
static __device__ __forceinline__ unsigned short bfb(__nv_bfloat16 h) {
    return *reinterpret_cast<unsigned short*>(&h);
}
__global__ void conv_split_kernel(const float* __restrict__ in,
                                  __nv_bfloat16* __restrict__ hi,
                                  __nv_bfloat16* __restrict__ lo, long long n4) {
    long long i = (long long)blockIdx.x * blockDim.x + threadIdx.x;
    if (i >= n4) return;
    float4 v = reinterpret_cast<const float4*>(in)[i];
    __nv_bfloat16 h0 = __float2bfloat16(v.x), h1 = __float2bfloat16(v.y);
    __nv_bfloat16 h2 = __float2bfloat16(v.z), h3 = __float2bfloat16(v.w);
    __nv_bfloat16 l0 = __float2bfloat16(v.x - __bfloat162float(h0));
    __nv_bfloat16 l1 = __float2bfloat16(v.y - __bfloat162float(h1));
    __nv_bfloat16 l2 = __float2bfloat16(v.z - __bfloat162float(h2));
    __nv_bfloat16 l3 = __float2bfloat16(v.w - __bfloat162float(h3));
    reinterpret_cast<ushort4*>(hi)[i] = make_ushort4(bfb(h0), bfb(h1), bfb(h2), bfb(h3));
    reinterpret_cast<ushort4*>(lo)[i] = make_ushort4(bfb(l0), bfb(l1), bfb(l2), bfb(l3));
}

// W[K,N] fp32 -> WT hi/lo bf16 [N,K]
__global__ void conv_wT_kernel(const float* __restrict__ W,
                               __nv_bfloat16* __restrict__ hi,
                               __nv_bfloat16* __restrict__ lo, int K, int N) {
    int idx = blockIdx.x * blockDim.x + threadIdx.x;
    if (idx >= K * N) return;
    int k = idx / N, n = idx % N;
    float v = W[idx];
    __nv_bfloat16 h = __float2bfloat16(v);
    __nv_bfloat16 l = __float2bfloat16(v - __bfloat162float(h));
    hi[(size_t)n * K + k] = h;
    lo[(size_t)n * K + k] = l;
}

// ---------------------------------------------------------------------------
// HMMA bf16 GEMM with K-TRIPLED hi/lo split:
//   C = Ahi@Bhi^T + Ahi@Blo^T + Alo@Bhi^T   (lo*lo dropped, ~2^-32)
// Chunk sections: [0,K)->(hi,hi), [K,2K)->(hi,lo), [2K,3K)->(lo,hi)
// Block tile 128x128, BK=32, 8 warps (each 64x32), mma.m16n8k16,
// cp.async 2-stage pipeline, swizzled smem + ldmatrix.x4.
// GCN epilogue writes C=hw and D = dinv[row]^2*C + bias.
// ---------------------------------------------------------------------------
#define STAGE_BYTES 16384

template<int KDIM, bool RELU, bool BIAS, bool GCN>
__global__ void __launch_bounds__(256, 2)
gemm_mma_kernel(const __nv_bfloat16* __restrict__ Ahi, const __nv_bfloat16* __restrict__ Alo,
                const __nv_bfloat16* __restrict__ Bhi, const __nv_bfloat16* __restrict__ Blo,
                const float* __restrict__ bias, const float* __restrict__ dinv,
                float* __restrict__ C, float* __restrict__ D,
                int M, int N) {
    __shared__ __align__(1024) char smem[2 * STAGE_BYTES];
    const uint32_t sbase = smem_u32(smem);

    const int tid  = threadIdx.x;
    const int lane = tid & 31;
    const int wid  = tid >> 5;
    const int wm   = wid >> 2;       // 0..1 -> 64 rows
    const int wn   = wid & 3;        // 0..3 -> 32 cols
    const int gq   = lane >> 2;      // mma group 0..7
    const int tq   = lane & 3;       // mma thread-in-group
    const int row0 = blockIdx.x * 128;
    const int col0 = blockIdx.y * 128;

    constexpr int NC = (3 * KDIM) / 32;   // K' chunks (3 sections)

    // pre-zero OOB A rows in both stages (B rows never OOB; loader skips OOB A)
    if (row0 + 127 >= M) {
        for (int f = tid; f < 512; f += 256) {
            int r = f >> 2, kq = f & 3;
            if (row0 + r >= M) {
                uint32_t off = (uint32_t)(r * 64 + ((kq ^ ((r >> 1) & 3)) * 16));
                asm volatile("st.shared.v4.b32 [%0], {%1,%1,%1,%1};" :: "r"(sbase + off), "r"(0u));
                asm volatile("st.shared.v4.b32 [%0], {%1,%1,%1,%1};" :: "r"(sbase + STAGE_BYTES + off), "r"(0u));
            }
        }
        __syncthreads();
    }

    float acc[4][4][4];
    #pragma unroll
    for (int i = 0; i < 4; i++)
        #pragma unroll
        for (int j = 0; j < 4; j++)
            #pragma unroll
            for (int q = 0; q < 4; q++) acc[i][j][q] = 0.0f;

    // ---- async tile loader
    auto load_stage = [&](int stage, int chunk) {
        const int kp  = chunk * 32;
        const int sec = kp / KDIM;                 // 0,1,2
        const int k0  = kp - sec * KDIM;
        const __nv_bfloat16* As = (sec == 2) ? Alo : Ahi;   // (hi,hi),(hi,lo),(lo,hi)
        const __nv_bfloat16* Bs = (sec == 1) ? Blo : Bhi;
        const uint32_t sA = sbase + stage * STAGE_BYTES;
        const uint32_t sB = sA + 8192;
        #pragma unroll
        for (int f = tid; f < 512; f += 256) {
            int r = f >> 2, kq = f & 3;
            uint32_t off = (uint32_t)(r * 64 + ((kq ^ ((r >> 1) & 3)) * 16));
            int gr = row0 + r;
            if (gr < M) CP_ASYNC16(sA + off, As + (size_t)gr * KDIM + k0 + kq * 8);
            CP_ASYNC16(sB + off, Bs + (size_t)(col0 + r) * KDIM + k0 + kq * 8);
        }
    };

    load_stage(0, 0);
    CP_COMMIT();

    for (int c = 0; c < NC; c++) {
        if (c + 1 < NC) load_stage((c + 1) & 1, c + 1);
        CP_COMMIT();
        CP_WAIT1();
        __syncthreads();

        const uint32_t sA = sbase + (c & 1) * STAGE_BYTES;
        const uint32_t sB = sA + 8192;

        #pragma unroll
        for (int ks = 0; ks < 2; ks++) {
            uint32_t a[4][4];
            #pragma unroll
            for (int mt = 0; mt < 4; mt++) {
                int r  = wm * 64 + mt * 16 + (lane & 15);
                int kq = (2 * ks + (lane >> 4)) ^ ((r >> 1) & 3);
                LDMATRIX_X4(a[mt][0], a[mt][1], a[mt][2], a[mt][3],
                            sA + (uint32_t)(r * 64 + kq * 16));
            }
            uint32_t b[4][2];
            #pragma unroll
            for (int pr = 0; pr < 2; pr++) {
                int r  = wn * 32 + pr * 16 + ((lane >> 4) & 1) * 8 + (lane & 7);
                int kq = (2 * ks + ((lane >> 3) & 1)) ^ ((r >> 1) & 3);
                LDMATRIX_X4(b[pr * 2][0], b[pr * 2][1], b[pr * 2 + 1][0], b[pr * 2 + 1][1],
                            sB + (uint32_t)(r * 64 + kq * 16));
            }
            #pragma unroll
            for (int mt = 0; mt < 4; mt++)
                #pragma unroll
                for (int nt = 0; nt < 4; nt++)
                    MMA16816(acc[mt][nt][0], acc[mt][nt][1], acc[mt][nt][2], acc[mt][nt][3],
                             a[mt][0], a[mt][1], a[mt][2], a[mt][3],
                             b[nt][0], b[nt][1]);
        }
        __syncthreads();
    }

    // ---- epilogue
    #pragma unroll
    for (int mt = 0; mt < 4; mt++) {
        int r0 = row0 + wm * 64 + mt * 16 + gq;
        int r1 = r0 + 8;
        float nm0 = 0.f, nm1 = 0.f;
        if (GCN) {
            if (r0 < M) { float d0 = dinv[r0]; nm0 = d0 * d0; }
            if (r1 < M) { float d1 = dinv[r1]; nm1 = d1 * d1; }
        }
        #pragma unroll
        for (int nt = 0; nt < 4; nt++) {
            int gc = col0 + wn * 32 + nt * 8 + tq * 2;
            float2 bb = make_float2(0.f, 0.f);
            if (BIAS || GCN) bb = *reinterpret_cast<const float2*>(&bias[gc]);
            float2 v0 = make_float2(acc[mt][nt][0], acc[mt][nt][1]);
            float2 v1 = make_float2(acc[mt][nt][2], acc[mt][nt][3]);
            if (BIAS) { v0.x += bb.x; v0.y += bb.y; v1.x += bb.x; v1.y += bb.y; }
            if (RELU) {
                v0.x = fmaxf(v0.x, 0.f); v0.y = fmaxf(v0.y, 0.f);
                v1.x = fmaxf(v1.x, 0.f); v1.y = fmaxf(v1.y, 0.f);
            }
            if (r0 < M) {
                *reinterpret_cast<float2*>(&C[(size_t)r0 * N + gc]) = v0;
                if (GCN) {
                    float2 w = make_float2(fmaf(v0.x, nm0, bb.x), fmaf(v0.y, nm0, bb.y));
                    *reinterpret_cast<float2*>(&D[(size_t)r0 * N + gc]) = w;
                }
            }
            if (r1 < M) {
                *reinterpret_cast<float2*>(&C[(size_t)r1 * N + gc]) = v1;
                if (GCN) {
                    float2 w = make_float2(fmaf(v1.x, nm1, bb.x), fmaf(v1.y, nm1, bb.y));
                    *reinterpret_cast<float2*>(&D[(size_t)r1 * N + gc]) = w;
                }
            }
        }
    }
}

// ---------------------------------------------------------------------------
// edge scatter: out[dst] += dinv[src]*dinv[dst] * hw[src]
// ---------------------------------------------------------------------------
__global__ void scatter_kernel(const float* __restrict__ hw,
                               const int* __restrict__ src,
                               const int* __restrict__ dst,
                               const float* __restrict__ dinv,
                               float* __restrict__ out) {
    long long idx = (long long)blockIdx.x * blockDim.x + threadIdx.x;
    int e = (int)(idx >> 7);
    if (e >= N_EDGES) return;
    int lane = (int)(idx & 127);
    int s = __ldg(&src[e]), d = __ldg(&dst[e]);
    float nm = __ldg(&dinv[s]) * __ldg(&dinv[d]);
    float4 v = reinterpret_cast<const float4*>(hw + (size_t)s * D_HID)[lane];
    v.x *= nm; v.y *= nm; v.z *= nm; v.w *= nm;
    float* addr = out + (size_t)d * D_HID + lane * 4;
    asm volatile("red.global.add.v4.f32 [%0], {%1,%2,%3,%4};"
                 :: "l"(addr), "f"(v.x), "f"(v.y), "f"(v.z), "f"(v.w)
                 : "memory");
}

// ---------------------------------------------------------------------------
extern "C" void kernel_launch(void* const* d_in, const int* in_sizes, int n_in,
                              void* d_out, int out_size) {
    const float* x  = (const float*)d_in[0];
    const int*   ei = (const int*)  d_in[1];
    const float* W1 = (const float*)d_in[2];
    const float* b1 = (const float*)d_in[3];
    const float* Wc = (const float*)d_in[4];
    const float* bc = (const float*)d_in[5];
    const float* W2 = (const float*)d_in[6];
    const float* b2 = (const float*)d_in[7];
    float* out = (float*)d_out;

    float *h0, *h1, *hw, *deg, *dinv;
    __nv_bfloat16 *ahi, *alo, *whi, *wlo;
    cudaGetSymbolAddress((void**)&h0,   g_h0);
    cudaGetSymbolAddress((void**)&h1,   g_h1);
    cudaGetSymbolAddress((void**)&hw,   g_hw);
    cudaGetSymbolAddress((void**)&deg,  g_deg);
    cudaGetSymbolAddress((void**)&dinv, g_dinv);
    cudaGetSymbolAddress((void**)&ahi,  g_ahi);
    cudaGetSymbolAddress((void**)&alo,  g_alo);
    cudaGetSymbolAddress((void**)&whi,  g_whi);
    cudaGetSymbolAddress((void**)&wlo,  g_wlo);

    const int* srcI = ei;
    const int* dstI = ei + N_EDGES;

    deg_init_kernel <<<(N_NODES + 255) / 256, 256>>>(deg);
    deg_accum_kernel<<<(N_EDGES + 255) / 256, 256>>>(dstI, deg);
    dinv_kernel     <<<(N_NODES + 255) / 256, 256>>>(deg, dinv);

    conv_wT_kernel<<<(D_IN * D_HID + 255) / 256, 256>>>(W1, whi + W1T_OFF, wlo + W1T_OFF, D_IN, D_HID);
    for (int l = 0; l < N_LAYERS; l++)
        conv_wT_kernel<<<(D_HID * D_HID + 255) / 256, 256>>>(
            Wc + (size_t)l * D_HID * D_HID,
            whi + WCT_OFF + (size_t)l * D_HID * D_HID,
            wlo + WCT_OFF + (size_t)l * D_HID * D_HID, D_HID, D_HID);
    conv_wT_kernel<<<(D_HID * D_OUT + 255) / 256, 256>>>(W2, whi + W2T_OFF, wlo + W2T_OFF, D_HID, D_OUT);

    const int GRID_M = (N_NODES + 127) / 128;   // 391
    const int sc_blocks = (int)(((long long)N_EDGES * 128 + 255) / 256);

    // dnn1: h0 = relu(x @ W1 + b1)
    {
        long long n4 = (long long)N_NODES * D_IN / 4;
        conv_split_kernel<<<(int)((n4 + 255) / 256), 256>>>(x, ahi, alo, n4);
        dim3 g(GRID_M, D_HID / 128);
        gemm_mma_kernel<D_IN, true, true, false><<<g, 256>>>(
            ahi, alo, whi + W1T_OFF, wlo + W1T_OFF, b1, nullptr, h0, nullptr,
            N_NODES, D_HID);
    }

    float* hc = h0;
    float* hn = h1;
    const long long n4h = (long long)N_NODES * D_HID / 4;
    for (int l = 0; l < N_LAYERS; l++) {
        conv_split_kernel<<<(int)((n4h + 255) / 256), 256>>>(hc, ahi, alo, n4h);
        dim3 g(GRID_M, D_HID / 128);
        gemm_mma_kernel<D_HID, false, false, true><<<g, 256>>>(
            ahi, alo,
            whi + WCT_OFF + (size_t)l * D_HID * D_HID,
            wlo + WCT_OFF + (size_t)l * D_HID * D_HID,
            bc + (size_t)l * D_HID, dinv, hw, hn,
            N_NODES, D_HID);
        scatter_kernel<<<sc_blocks, 256>>>(hw, srcI, dstI, dinv, hn);
        float* t = hc; hc = hn; hn = t;
    }

    // dnn2: out = hc @ W2 + b2
    {
        conv_split_kernel<<<(int)((n4h + 255) / 256), 256>>>(hc, ahi, alo, n4h);
        dim3 g(GRID_M, D_OUT / 128);
        gemm_mma_kernel<D_HID, false, true, false><<<g, 256>>>(
            ahi, alo, whi + W2T_OFF, wlo + W2T_OFF, b2, nullptr, out, nullptr,
            N_NODES, D_OUT);
    }
}

// round 7
// speedup vs baseline: 3.9417x; 1.5526x over previous
#include <cuda_runtime.h>
#include <cuda_bf16.h>
#include <cstdint>

#define N_NODES 50000
#define N_EDGES 400000
#define D_IN    256
#define D_HID   512
#define D_OUT   128
#define N_LAYERS 4
#define SCAN_NB 49   // ceil(50000/1024)

// ---------------------------------------------------------------------------
// Scratch (__device__ globals; allocation-free rule)
// ---------------------------------------------------------------------------
__device__ float g_hw[(size_t)N_NODES * D_HID];
__device__ float g_dinv[N_NODES];
__device__ __align__(16) __nv_bfloat16 g_ahi[(size_t)N_NODES * D_HID];  // x split
__device__ __align__(16) __nv_bfloat16 g_alo[(size_t)N_NODES * D_HID];
__device__ __align__(16) __nv_bfloat16 g_bhi[(size_t)N_NODES * D_HID];  // h split
__device__ __align__(16) __nv_bfloat16 g_blo[(size_t)N_NODES * D_HID];
// CSR
__device__ int g_rowcnt[N_NODES];
__device__ int g_cursor[N_NODES];
__device__ int g_rowptr[N_NODES + 1];
__device__ int g_bsum[64];
__device__ int g_csrsrc[N_EDGES];
// transposed weights, bf16 hi/lo
#define W1T_OFF 0
#define WCT_OFF (D_HID * D_IN)
#define W2T_OFF (WCT_OFF + N_LAYERS * D_HID * D_HID)
#define W_TOTAL (W2T_OFF + D_OUT * D_HID)
__device__ __align__(16) __nv_bfloat16 g_whi[W_TOTAL];
__device__ __align__(16) __nv_bfloat16 g_wlo[W_TOTAL];

// ---------------------------------------------------------------------------
static __device__ __forceinline__ uint32_t smem_u32(const void* p) {
    uint32_t a;
    asm("{ .reg .u64 t; cvta.to.shared.u64 t, %1; cvt.u32.u64 %0, t; }" : "=r"(a) : "l"(p));
    return a;
}

#define CP_ASYNC16(dst, src) \
    asm volatile("cp.async.cg.shared.global [%0], [%1], 16;" :: "r"(dst), "l"(src) : "memory")
#define CP_COMMIT() asm volatile("cp.async.commit_group;" ::: "memory")
#define CP_WAIT1()  asm volatile("cp.async.wait_group 1;"  ::: "memory")

#define LDMATRIX_X4(r0, r1, r2, r3, addr) \
    asm volatile("ldmatrix.sync.aligned.m8n8.x4.shared.b16 {%0,%1,%2,%3}, [%4];" \
                 : "=r"(r0), "=r"(r1), "=r"(r2), "=r"(r3) : "r"(addr))

#define MMA16816(c0, c1, c2, c3, a0, a1, a2, a3, b0, b1) \
    asm volatile("mma.sync.aligned.m16n8k16.row.col.f32.bf16.bf16.f32 " \
                 "{%0,%1,%2,%3}, {%4,%5,%6,%7}, {%8,%9}, {%0,%1,%2,%3};" \
                 : "+f"(c0), "+f"(c1), "+f"(c2), "+f"(c3) \
                 : "r"(a0), "r"(a1), "r"(a2), "r"(a3), "r"(b0), "r"(b1))

static __device__ __forceinline__ unsigned short bfb(__nv_bfloat16 h) {
    return *reinterpret_cast<unsigned short*>(&h);
}
static __device__ __forceinline__ void split2(float x, float y, unsigned short& h2x,
                                              unsigned short& h2y, unsigned short& l2x,
                                              unsigned short& l2y) {
    __nv_bfloat16 hx = __float2bfloat16(x), hy = __float2bfloat16(y);
    __nv_bfloat16 lx = __float2bfloat16(x - __bfloat162float(hx));
    __nv_bfloat16 ly = __float2bfloat16(y - __bfloat162float(hy));
    h2x = bfb(hx); h2y = bfb(hy); l2x = bfb(lx); l2y = bfb(ly);
}

// ---------------------------------------------------------------------------
// CSR build + dinv
// ---------------------------------------------------------------------------
__global__ void hist_zero_kernel(int* __restrict__ cnt, int* __restrict__ cur) {
    int n = blockIdx.x * blockDim.x + threadIdx.x;
    if (n < N_NODES) { cnt[n] = 0; cur[n] = 0; }
}
__global__ void hist_kernel(const int* __restrict__ dst, int* __restrict__ cnt) {
    int e = blockIdx.x * blockDim.x + threadIdx.x;
    if (e < N_EDGES) atomicAdd(&cnt[dst[e]], 1);
}
__global__ void scan_local_kernel(const int* __restrict__ cnt, int* __restrict__ rptr,
                                  int* __restrict__ bsum) {
    __shared__ int sh[1024];
    int t = threadIdx.x;
    int i = blockIdx.x * 1024 + t;
    int v = (i < N_NODES) ? cnt[i] : 0;
    sh[t] = v;
    __syncthreads();
    #pragma unroll
    for (int off = 1; off < 1024; off <<= 1) {
        int x = 0;
        if (t >= off) x = sh[t - off];
        __syncthreads();
        if (t >= off) sh[t] += x;
        __syncthreads();
    }
    if (i < N_NODES) rptr[i] = sh[t] - v;   // exclusive
    if (t == 1023) bsum[blockIdx.x] = sh[1023];
}
__global__ void scan_blocks_kernel(int* __restrict__ bsum) {
    if (threadIdx.x == 0) {
        int run = 0;
        for (int b = 0; b < SCAN_NB; b++) { int x = bsum[b]; bsum[b] = run; run += x; }
    }
}
__global__ void scan_add_kernel(int* __restrict__ rptr, const int* __restrict__ bsum) {
    int i = blockIdx.x * blockDim.x + threadIdx.x;
    if (i < N_NODES) rptr[i] += bsum[i >> 10];
    if (i == 0) rptr[N_NODES] = N_EDGES;
}
__global__ void fill_kernel(const int* __restrict__ src, const int* __restrict__ dst,
                            const int* __restrict__ rptr, int* __restrict__ cur,
                            int* __restrict__ csrsrc) {
    int e = blockIdx.x * blockDim.x + threadIdx.x;
    if (e >= N_EDGES) return;
    int d = dst[e];
    int pos = rptr[d] + atomicAdd(&cur[d], 1);
    csrsrc[pos] = src[e];
}
__global__ void dinv_kernel(const int* __restrict__ cnt, float* __restrict__ dinv) {
    int n = blockIdx.x * blockDim.x + threadIdx.x;
    if (n < N_NODES) dinv[n] = rsqrtf((float)cnt[n] + 1.0f);
}

// ---------------------------------------------------------------------------
// x fp32 -> bf16 hi/lo (input features only)
// ---------------------------------------------------------------------------
__global__ void conv_split_kernel(const float* __restrict__ in,
                                  __nv_bfloat16* __restrict__ hi,
                                  __nv_bfloat16* __restrict__ lo, long long n4) {
    long long i = (long long)blockIdx.x * blockDim.x + threadIdx.x;
    if (i >= n4) return;
    float4 v = reinterpret_cast<const float4*>(in)[i];
    unsigned short hx, hy, hz, hwv, lx, ly, lz, lw;
    split2(v.x, v.y, hx, hy, lx, ly);
    split2(v.z, v.w, hz, hwv, lz, lw);
    reinterpret_cast<ushort4*>(hi)[i] = make_ushort4(hx, hy, hz, hwv);
    reinterpret_cast<ushort4*>(lo)[i] = make_ushort4(lx, ly, lz, lw);
}

// W[K,N] fp32 -> WT hi/lo bf16 [N,K]
__global__ void conv_wT_kernel(const float* __restrict__ W,
                               __nv_bfloat16* __restrict__ hi,
                               __nv_bfloat16* __restrict__ lo, int K, int N) {
    int idx = blockIdx.x * blockDim.x + threadIdx.x;
    if (idx >= K * N) return;
    int k = idx / N, n = idx % N;
    float v = W[idx];
    __nv_bfloat16 h = __float2bfloat16(v);
    __nv_bfloat16 l = __float2bfloat16(v - __bfloat162float(h));
    hi[(size_t)n * K + k] = h;
    lo[(size_t)n * K + k] = l;
}

// ---------------------------------------------------------------------------
// HMMA bf16 GEMM, K-tripled hi/lo (hi*hi + hi*lo + lo*hi).
// MODE 0: dnn1   — bias+relu, write split bf16 hi/lo (to DIFFERENT buffers)
// MODE 1: conv   — write fp32 C only (hw)
// MODE 2: dnn2   — bias, write fp32 C
// ---------------------------------------------------------------------------
#define STAGE_BYTES 16384

template<int KDIM, int MODE>
__global__ void __launch_bounds__(256, 2)
gemm_mma_kernel(const __nv_bfloat16* __restrict__ Ahi, const __nv_bfloat16* __restrict__ Alo,
                const __nv_bfloat16* __restrict__ Bhi, const __nv_bfloat16* __restrict__ Blo,
                const float* __restrict__ bias,
                float* __restrict__ C,
                __nv_bfloat16* __restrict__ Ohi, __nv_bfloat16* __restrict__ Olo,
                int M, int N) {
    __shared__ __align__(1024) char smem[2 * STAGE_BYTES];
    const uint32_t sbase = smem_u32(smem);

    const int tid  = threadIdx.x;
    const int lane = tid & 31;
    const int wid  = tid >> 5;
    const int wm   = wid >> 2;
    const int wn   = wid & 3;
    const int gq   = lane >> 2;
    const int tq   = lane & 3;
    const int row0 = blockIdx.x * 128;
    const int col0 = blockIdx.y * 128;

    constexpr int NC = (3 * KDIM) / 32;

    if (row0 + 127 >= M) {
        for (int f = tid; f < 512; f += 256) {
            int r = f >> 2, kq = f & 3;
            if (row0 + r >= M) {
                uint32_t off = (uint32_t)(r * 64 + ((kq ^ ((r >> 1) & 3)) * 16));
                asm volatile("st.shared.v4.b32 [%0], {%1,%1,%1,%1};" :: "r"(sbase + off), "r"(0u));
                asm volatile("st.shared.v4.b32 [%0], {%1,%1,%1,%1};" :: "r"(sbase + STAGE_BYTES + off), "r"(0u));
            }
        }
        __syncthreads();
    }

    float acc[4][4][4];
    #pragma unroll
    for (int i = 0; i < 4; i++)
        #pragma unroll
        for (int j = 0; j < 4; j++)
            #pragma unroll
            for (int q = 0; q < 4; q++) acc[i][j][q] = 0.0f;

    auto load_stage = [&](int stage, int chunk) {
        const int kp  = chunk * 32;
        const int sec = kp / KDIM;
        const int k0  = kp - sec * KDIM;
        const __nv_bfloat16* As = (sec == 2) ? Alo : Ahi;
        const __nv_bfloat16* Bs = (sec == 1) ? Blo : Bhi;
        const uint32_t sA = sbase + stage * STAGE_BYTES;
        const uint32_t sB = sA + 8192;
        #pragma unroll
        for (int f = tid; f < 512; f += 256) {
            int r = f >> 2, kq = f & 3;
            uint32_t off = (uint32_t)(r * 64 + ((kq ^ ((r >> 1) & 3)) * 16));
            int gr = row0 + r;
            if (gr < M) CP_ASYNC16(sA + off, As + (size_t)gr * KDIM + k0 + kq * 8);
            CP_ASYNC16(sB + off, Bs + (size_t)(col0 + r) * KDIM + k0 + kq * 8);
        }
    };

    load_stage(0, 0);
    CP_COMMIT();

    for (int c = 0; c < NC; c++) {
        if (c + 1 < NC) load_stage((c + 1) & 1, c + 1);
        CP_COMMIT();
        CP_WAIT1();
        __syncthreads();

        const uint32_t sA = sbase + (c & 1) * STAGE_BYTES;
        const uint32_t sB = sA + 8192;

        #pragma unroll
        for (int ks = 0; ks < 2; ks++) {
            uint32_t a[4][4];
            #pragma unroll
            for (int mt = 0; mt < 4; mt++) {
                int r  = wm * 64 + mt * 16 + (lane & 15);
                int kq = (2 * ks + (lane >> 4)) ^ ((r >> 1) & 3);
                LDMATRIX_X4(a[mt][0], a[mt][1], a[mt][2], a[mt][3],
                            sA + (uint32_t)(r * 64 + kq * 16));
            }
            uint32_t b[4][2];
            #pragma unroll
            for (int pr = 0; pr < 2; pr++) {
                int r  = wn * 32 + pr * 16 + ((lane >> 4) & 1) * 8 + (lane & 7);
                int kq = (2 * ks + ((lane >> 3) & 1)) ^ ((r >> 1) & 3);
                LDMATRIX_X4(b[pr * 2][0], b[pr * 2][1], b[pr * 2 + 1][0], b[pr * 2 + 1][1],
                            sB + (uint32_t)(r * 64 + kq * 16));
            }
            #pragma unroll
            for (int mt = 0; mt < 4; mt++)
                #pragma unroll
                for (int nt = 0; nt < 4; nt++)
                    MMA16816(acc[mt][nt][0], acc[mt][nt][1], acc[mt][nt][2], acc[mt][nt][3],
                             a[mt][0], a[mt][1], a[mt][2], a[mt][3],
                             b[nt][0], b[nt][1]);
        }
        __syncthreads();
    }

    // epilogue
    #pragma unroll
    for (int mt = 0; mt < 4; mt++) {
        int r0 = row0 + wm * 64 + mt * 16 + gq;
        int r1 = r0 + 8;
        #pragma unroll
        for (int nt = 0; nt < 4; nt++) {
            int gc = col0 + wn * 32 + nt * 8 + tq * 2;
            float2 bb = make_float2(0.f, 0.f);
            if (MODE != 1) bb = *reinterpret_cast<const float2*>(&bias[gc]);
            float2 v0 = make_float2(acc[mt][nt][0], acc[mt][nt][1]);
            float2 v1 = make_float2(acc[mt][nt][2], acc[mt][nt][3]);
            if (MODE != 1) { v0.x += bb.x; v0.y += bb.y; v1.x += bb.x; v1.y += bb.y; }
            if (MODE == 0) {
                v0.x = fmaxf(v0.x, 0.f); v0.y = fmaxf(v0.y, 0.f);
                v1.x = fmaxf(v1.x, 0.f); v1.y = fmaxf(v1.y, 0.f);
            }
            if (r0 < M) {
                if (MODE == 0) {
                    unsigned short hx, hy, lx, ly;
                    split2(v0.x, v0.y, hx, hy, lx, ly);
                    *reinterpret_cast<ushort2*>(&Ohi[(size_t)r0 * N + gc]) = make_ushort2(hx, hy);
                    *reinterpret_cast<ushort2*>(&Olo[(size_t)r0 * N + gc]) = make_ushort2(lx, ly);
                } else {
                    *reinterpret_cast<float2*>(&C[(size_t)r0 * N + gc]) = v0;
                }
            }
            if (r1 < M) {
                if (MODE == 0) {
                    unsigned short hx, hy, lx, ly;
                    split2(v1.x, v1.y, hx, hy, lx, ly);
                    *reinterpret_cast<ushort2*>(&Ohi[(size_t)r1 * N + gc]) = make_ushort2(hx, hy);
                    *reinterpret_cast<ushort2*>(&Olo[(size_t)r1 * N + gc]) = make_ushort2(lx, ly);
                } else {
                    *reinterpret_cast<float2*>(&C[(size_t)r1 * N + gc]) = v1;
                }
            }
        }
    }
}

// ---------------------------------------------------------------------------
// CSR aggregation: one warp per node.
//   h[n] = bias + dinv[n]^2*hw[n] + sum_e dinv[src]*dinv[n]*hw[src]
// Output written directly as bf16 hi/lo for the next GEMM.
// ---------------------------------------------------------------------------
__global__ void __launch_bounds__(256)
agg_kernel(const float* __restrict__ hw,
           const int* __restrict__ rowptr, const int* __restrict__ csrsrc,
           const float* __restrict__ dinv, const float* __restrict__ bias,
           __nv_bfloat16* __restrict__ ohi, __nv_bfloat16* __restrict__ olo) {
    int warp = (blockIdx.x * blockDim.x + threadIdx.x) >> 5;
    if (warp >= N_NODES) return;
    const int lane = threadIdx.x & 31;
    const int n = warp;
    const float di = __ldg(&dinv[n]);
    const float nm = di * di;

    float4 acc[4];
    const float4* self4 = reinterpret_cast<const float4*>(hw + (size_t)n * D_HID);
    const float4* bias4 = reinterpret_cast<const float4*>(bias);
    #pragma unroll
    for (int k = 0; k < 4; k++) {
        float4 b = __ldg(bias4 + lane + 32 * k);
        float4 v = __ldg(self4 + lane + 32 * k);
        acc[k].x = fmaf(v.x, nm, b.x);
        acc[k].y = fmaf(v.y, nm, b.y);
        acc[k].z = fmaf(v.z, nm, b.z);
        acc[k].w = fmaf(v.w, nm, b.w);
    }

    const int e0 = __ldg(&rowptr[n]);
    const int e1 = __ldg(&rowptr[n + 1]);
    for (int e = e0; e < e1; e++) {
        int s = __ldg(&csrsrc[e]);
        float w = __ldg(&dinv[s]) * di;
        const float4* row = reinterpret_cast<const float4*>(hw + (size_t)s * D_HID);
        #pragma unroll
        for (int k = 0; k < 4; k++) {
            float4 v = __ldg(row + lane + 32 * k);
            acc[k].x = fmaf(v.x, w, acc[k].x);
            acc[k].y = fmaf(v.y, w, acc[k].y);
            acc[k].z = fmaf(v.z, w, acc[k].z);
            acc[k].w = fmaf(v.w, w, acc[k].w);
        }
    }

    #pragma unroll
    for (int k = 0; k < 4; k++) {
        size_t base = (size_t)n * D_HID + lane * 4 + 128 * k;
        unsigned short hx, hy, hz, hwv, lx, ly, lz, lw;
        split2(acc[k].x, acc[k].y, hx, hy, lx, ly);
        split2(acc[k].z, acc[k].w, hz, hwv, lz, lw);
        *reinterpret_cast<ushort4*>(ohi + base) = make_ushort4(hx, hy, hz, hwv);
        *reinterpret_cast<ushort4*>(olo + base) = make_ushort4(lx, ly, lz, lw);
    }
}

// ---------------------------------------------------------------------------
extern "C" void kernel_launch(void* const* d_in, const int* in_sizes, int n_in,
                              void* d_out, int out_size) {
    const float* x  = (const float*)d_in[0];
    const int*   ei = (const int*)  d_in[1];
    const float* W1 = (const float*)d_in[2];
    const float* b1 = (const float*)d_in[3];
    const float* Wc = (const float*)d_in[4];
    const float* bc = (const float*)d_in[5];
    const float* W2 = (const float*)d_in[6];
    const float* b2 = (const float*)d_in[7];
    float* out = (float*)d_out;

    float *hw, *dinv;
    __nv_bfloat16 *ahi, *alo, *bhi, *blo, *whi, *wlo;
    int *rowcnt, *cursor, *rowptr, *bsum, *csrsrc;
    cudaGetSymbolAddress((void**)&hw,     g_hw);
    cudaGetSymbolAddress((void**)&dinv,   g_dinv);
    cudaGetSymbolAddress((void**)&ahi,    g_ahi);
    cudaGetSymbolAddress((void**)&alo,    g_alo);
    cudaGetSymbolAddress((void**)&bhi,    g_bhi);
    cudaGetSymbolAddress((void**)&blo,    g_blo);
    cudaGetSymbolAddress((void**)&whi,    g_whi);
    cudaGetSymbolAddress((void**)&wlo,    g_wlo);
    cudaGetSymbolAddress((void**)&rowcnt, g_rowcnt);
    cudaGetSymbolAddress((void**)&cursor, g_cursor);
    cudaGetSymbolAddress((void**)&rowptr, g_rowptr);
    cudaGetSymbolAddress((void**)&bsum,   g_bsum);
    cudaGetSymbolAddress((void**)&csrsrc, g_csrsrc);

    const int* srcI = ei;
    const int* dstI = ei + N_EDGES;

    // CSR build + dinv
    hist_zero_kernel<<<(N_NODES + 255) / 256, 256>>>(rowcnt, cursor);
    hist_kernel     <<<(N_EDGES + 255) / 256, 256>>>(dstI, rowcnt);
    scan_local_kernel<<<SCAN_NB, 1024>>>(rowcnt, rowptr, bsum);
    scan_blocks_kernel<<<1, 32>>>(bsum);
    scan_add_kernel <<<(N_NODES + 255) / 256, 256>>>(rowptr, bsum);
    fill_kernel     <<<(N_EDGES + 255) / 256, 256>>>(srcI, dstI, rowptr, cursor, csrsrc);
    dinv_kernel     <<<(N_NODES + 255) / 256, 256>>>(rowcnt, dinv);

    // weights -> transposed bf16 hi/lo
    conv_wT_kernel<<<(D_IN * D_HID + 255) / 256, 256>>>(W1, whi + W1T_OFF, wlo + W1T_OFF, D_IN, D_HID);
    for (int l = 0; l < N_LAYERS; l++)
        conv_wT_kernel<<<(D_HID * D_HID + 255) / 256, 256>>>(
            Wc + (size_t)l * D_HID * D_HID,
            whi + WCT_OFF + (size_t)l * D_HID * D_HID,
            wlo + WCT_OFF + (size_t)l * D_HID * D_HID, D_HID, D_HID);
    conv_wT_kernel<<<(D_HID * D_OUT + 255) / 256, 256>>>(W2, whi + W2T_OFF, wlo + W2T_OFF, D_HID, D_OUT);

    const int GRID_M = (N_NODES + 127) / 128;

    // x -> hi/lo (ahi/alo)
    {
        long long n4 = (long long)N_NODES * D_IN / 4;
        conv_split_kernel<<<(int)((n4 + 255) / 256), 256>>>(x, ahi, alo, n4);
    }

    // dnn1: split(relu(x @ W1 + b1)) -> bhi/blo   (distinct from input!)
    {
        dim3 g(GRID_M, D_HID / 128);
        gemm_mma_kernel<D_IN, 0><<<g, 256>>>(
            ahi, alo, whi + W1T_OFF, wlo + W1T_OFF, b1, nullptr, bhi, blo,
            N_NODES, D_HID);
    }

    const int agg_blocks = (N_NODES * 32 + 255) / 256;
    for (int l = 0; l < N_LAYERS; l++) {
        // GEMM consumes bhi/blo fully before agg relaunches into them
        dim3 g(GRID_M, D_HID / 128);
        gemm_mma_kernel<D_HID, 1><<<g, 256>>>(
            bhi, blo,
            whi + WCT_OFF + (size_t)l * D_HID * D_HID,
            wlo + WCT_OFF + (size_t)l * D_HID * D_HID,
            nullptr, hw, nullptr, nullptr,
            N_NODES, D_HID);
        agg_kernel<<<agg_blocks, 256>>>(hw, rowptr, csrsrc, dinv,
                                        bc + (size_t)l * D_HID, bhi, blo);
    }

    // dnn2: out = h @ W2 + b2
    {
        dim3 g(GRID_M, D_OUT / 128);
        gemm_mma_kernel<D_HID, 2><<<g, 256>>>(
            bhi, blo, whi + W2T_OFF, wlo + W2T_OFF, b2, out, nullptr, nullptr,
            N_NODES, D_OUT);
    }
}

// round 8
// speedup vs baseline: 5.0134x; 1.2719x over previous
#include <cuda_runtime.h>
#include <cuda_fp16.h>
#include <cstdint>

#define N_NODES 50000
#define N_EDGES 400000
#define D_IN    256
#define D_HID   512
#define D_OUT   128
#define N_LAYERS 4
#define SCAN_NB 49   // ceil(50000/1024)

// ---------------------------------------------------------------------------
// Scratch (__device__ globals; allocation-free rule)
// ---------------------------------------------------------------------------
__device__ float g_hw[(size_t)N_NODES * D_HID];
__device__ float g_dinv[N_NODES];
__device__ __align__(16) __half g_ahi[(size_t)N_NODES * D_HID];  // x split
__device__ __align__(16) __half g_alo[(size_t)N_NODES * D_HID];
__device__ __align__(16) __half g_bhi[(size_t)N_NODES * D_HID];  // h split
__device__ __align__(16) __half g_blo[(size_t)N_NODES * D_HID];
// CSR
__device__ int g_rowcnt[N_NODES];
__device__ int g_cursor[N_NODES];
__device__ int g_rowptr[N_NODES + 1];
__device__ int g_bsum[64];
__device__ int g_csrsrc[N_EDGES];
// transposed weights, fp16 hi only: W1T[512,256] | WcT[4][512,512] | W2T[128,512]
#define W1T_OFF 0
#define WCT_OFF (D_HID * D_IN)
#define W2T_OFF (WCT_OFF + N_LAYERS * D_HID * D_HID)
#define W_TOTAL (W2T_OFF + D_OUT * D_HID)
__device__ __align__(16) __half g_whi[W_TOTAL];

// ---------------------------------------------------------------------------
static __device__ __forceinline__ uint32_t smem_u32(const void* p) {
    uint32_t a;
    asm("{ .reg .u64 t; cvta.to.shared.u64 t, %1; cvt.u32.u64 %0, t; }" : "=r"(a) : "l"(p));
    return a;
}

#define CP_ASYNC16(dst, src) \
    asm volatile("cp.async.cg.shared.global [%0], [%1], 16;" :: "r"(dst), "l"(src) : "memory")
#define CP_COMMIT() asm volatile("cp.async.commit_group;" ::: "memory")
#define CP_WAIT1()  asm volatile("cp.async.wait_group 1;"  ::: "memory")

#define LDMATRIX_X4(r0, r1, r2, r3, addr) \
    asm volatile("ldmatrix.sync.aligned.m8n8.x4.shared.b16 {%0,%1,%2,%3}, [%4];" \
                 : "=r"(r0), "=r"(r1), "=r"(r2), "=r"(r3) : "r"(addr))

#define MMA16816(c0, c1, c2, c3, a0, a1, a2, a3, b0, b1) \
    asm volatile("mma.sync.aligned.m16n8k16.row.col.f32.f16.f16.f32 " \
                 "{%0,%1,%2,%3}, {%4,%5,%6,%7}, {%8,%9}, {%0,%1,%2,%3};" \
                 : "+f"(c0), "+f"(c1), "+f"(c2), "+f"(c3) \
                 : "r"(a0), "r"(a1), "r"(a2), "r"(a3), "r"(b0), "r"(b1))

static __device__ __forceinline__ unsigned short hfb(__half h) {
    return *reinterpret_cast<unsigned short*>(&h);
}
// fp16 hi/lo split of two floats
static __device__ __forceinline__ void split2(float x, float y, unsigned short& h2x,
                                              unsigned short& h2y, unsigned short& l2x,
                                              unsigned short& l2y) {
    __half hx = __float2half_rn(x), hy = __float2half_rn(y);
    __half lx = __float2half_rn(x - __half2float(hx));
    __half ly = __float2half_rn(y - __half2float(hy));
    h2x = hfb(hx); h2y = hfb(hy); l2x = hfb(lx); l2y = hfb(ly);
}

// ---------------------------------------------------------------------------
// CSR build + dinv
// ---------------------------------------------------------------------------
__global__ void hist_zero_kernel(int* __restrict__ cnt, int* __restrict__ cur) {
    int n = blockIdx.x * blockDim.x + threadIdx.x;
    if (n < N_NODES) { cnt[n] = 0; cur[n] = 0; }
}
__global__ void hist_kernel(const int* __restrict__ dst, int* __restrict__ cnt) {
    int e = blockIdx.x * blockDim.x + threadIdx.x;
    if (e < N_EDGES) atomicAdd(&cnt[dst[e]], 1);
}
__global__ void scan_local_kernel(const int* __restrict__ cnt, int* __restrict__ rptr,
                                  int* __restrict__ bsum) {
    __shared__ int sh[1024];
    int t = threadIdx.x;
    int i = blockIdx.x * 1024 + t;
    int v = (i < N_NODES) ? cnt[i] : 0;
    sh[t] = v;
    __syncthreads();
    #pragma unroll
    for (int off = 1; off < 1024; off <<= 1) {
        int x = 0;
        if (t >= off) x = sh[t - off];
        __syncthreads();
        if (t >= off) sh[t] += x;
        __syncthreads();
    }
    if (i < N_NODES) rptr[i] = sh[t] - v;   // exclusive
    if (t == 1023) bsum[blockIdx.x] = sh[1023];
}
__global__ void scan_blocks_kernel(int* __restrict__ bsum) {
    if (threadIdx.x == 0) {
        int run = 0;
        for (int b = 0; b < SCAN_NB; b++) { int x = bsum[b]; bsum[b] = run; run += x; }
    }
}
__global__ void scan_add_kernel(int* __restrict__ rptr, const int* __restrict__ bsum) {
    int i = blockIdx.x * blockDim.x + threadIdx.x;
    if (i < N_NODES) rptr[i] += bsum[i >> 10];
    if (i == 0) rptr[N_NODES] = N_EDGES;
}
__global__ void fill_kernel(const int* __restrict__ src, const int* __restrict__ dst,
                            const int* __restrict__ rptr, int* __restrict__ cur,
                            int* __restrict__ csrsrc) {
    int e = blockIdx.x * blockDim.x + threadIdx.x;
    if (e >= N_EDGES) return;
    int d = dst[e];
    int pos = rptr[d] + atomicAdd(&cur[d], 1);
    csrsrc[pos] = src[e];
}
__global__ void dinv_kernel(const int* __restrict__ cnt, float* __restrict__ dinv) {
    int n = blockIdx.x * blockDim.x + threadIdx.x;
    if (n < N_NODES) dinv[n] = rsqrtf((float)cnt[n] + 1.0f);
}

// ---------------------------------------------------------------------------
// x fp32 -> fp16 hi/lo
// ---------------------------------------------------------------------------
__global__ void conv_split_kernel(const float* __restrict__ in,
                                  __half* __restrict__ hi,
                                  __half* __restrict__ lo, long long n4) {
    long long i = (long long)blockIdx.x * blockDim.x + threadIdx.x;
    if (i >= n4) return;
    float4 v = reinterpret_cast<const float4*>(in)[i];
    unsigned short hx, hy, hz, hwv, lx, ly, lz, lw;
    split2(v.x, v.y, hx, hy, lx, ly);
    split2(v.z, v.w, hz, hwv, lz, lw);
    reinterpret_cast<ushort4*>(hi)[i] = make_ushort4(hx, hy, hz, hwv);
    reinterpret_cast<ushort4*>(lo)[i] = make_ushort4(lx, ly, lz, lw);
}

// W[K,N] fp32 -> WT fp16 [N,K] (hi only)
__global__ void conv_wT_kernel(const float* __restrict__ W,
                               __half* __restrict__ hi, int K, int N) {
    int idx = blockIdx.x * blockDim.x + threadIdx.x;
    if (idx >= K * N) return;
    int k = idx / N, n = idx % N;
    hi[(size_t)n * K + k] = __float2half_rn(W[idx]);
}

// ---------------------------------------------------------------------------
// HMMA fp16 GEMM, K-doubled: C = (Ahi + Alo) @ Bhi^T  (exact in A, fp16 W)
// Sections: [0,K)->(Ahi,Bhi), [K,2K)->(Alo,Bhi)
// MODE 0: dnn1 — bias+relu, write fp16 hi/lo split (to different buffers)
// MODE 1: conv — write fp32 C (hw)
// MODE 2: dnn2 — bias, write fp32 C
// ---------------------------------------------------------------------------
#define STAGE_BYTES 16384

template<int KDIM, int MODE>
__global__ void __launch_bounds__(256, 2)
gemm_mma_kernel(const __half* __restrict__ Ahi, const __half* __restrict__ Alo,
                const __half* __restrict__ Bhi,
                const float* __restrict__ bias,
                float* __restrict__ C,
                __half* __restrict__ Ohi, __half* __restrict__ Olo,
                int M, int N) {
    __shared__ __align__(1024) char smem[2 * STAGE_BYTES];
    const uint32_t sbase = smem_u32(smem);

    const int tid  = threadIdx.x;
    const int lane = tid & 31;
    const int wid  = tid >> 5;
    const int wm   = wid >> 2;
    const int wn   = wid & 3;
    const int gq   = lane >> 2;
    const int tq   = lane & 3;
    const int row0 = blockIdx.x * 128;
    const int col0 = blockIdx.y * 128;

    constexpr int NC = (2 * KDIM) / 32;

    if (row0 + 127 >= M) {
        for (int f = tid; f < 512; f += 256) {
            int r = f >> 2, kq = f & 3;
            if (row0 + r >= M) {
                uint32_t off = (uint32_t)(r * 64 + ((kq ^ ((r >> 1) & 3)) * 16));
                asm volatile("st.shared.v4.b32 [%0], {%1,%1,%1,%1};" :: "r"(sbase + off), "r"(0u));
                asm volatile("st.shared.v4.b32 [%0], {%1,%1,%1,%1};" :: "r"(sbase + STAGE_BYTES + off), "r"(0u));
            }
        }
        __syncthreads();
    }

    float acc[4][4][4];
    #pragma unroll
    for (int i = 0; i < 4; i++)
        #pragma unroll
        for (int j = 0; j < 4; j++)
            #pragma unroll
            for (int q = 0; q < 4; q++) acc[i][j][q] = 0.0f;

    auto load_stage = [&](int stage, int chunk) {
        const int kp  = chunk * 32;
        const int sec = kp / KDIM;                 // 0: Ahi, 1: Alo
        const int k0  = kp - sec * KDIM;
        const __half* As = sec ? Alo : Ahi;
        const uint32_t sA = sbase + stage * STAGE_BYTES;
        const uint32_t sB = sA + 8192;
        #pragma unroll
        for (int f = tid; f < 512; f += 256) {
            int r = f >> 2, kq = f & 3;
            uint32_t off = (uint32_t)(r * 64 + ((kq ^ ((r >> 1) & 3)) * 16));
            int gr = row0 + r;
            if (gr < M) CP_ASYNC16(sA + off, As + (size_t)gr * KDIM + k0 + kq * 8);
            CP_ASYNC16(sB + off, Bhi + (size_t)(col0 + r) * KDIM + k0 + kq * 8);
        }
    };

    load_stage(0, 0);
    CP_COMMIT();

    for (int c = 0; c < NC; c++) {
        if (c + 1 < NC) load_stage((c + 1) & 1, c + 1);
        CP_COMMIT();
        CP_WAIT1();
        __syncthreads();

        const uint32_t sA = sbase + (c & 1) * STAGE_BYTES;
        const uint32_t sB = sA + 8192;

        #pragma unroll
        for (int ks = 0; ks < 2; ks++) {
            uint32_t a[4][4];
            #pragma unroll
            for (int mt = 0; mt < 4; mt++) {
                int r  = wm * 64 + mt * 16 + (lane & 15);
                int kq = (2 * ks + (lane >> 4)) ^ ((r >> 1) & 3);
                LDMATRIX_X4(a[mt][0], a[mt][1], a[mt][2], a[mt][3],
                            sA + (uint32_t)(r * 64 + kq * 16));
            }
            uint32_t b[4][2];
            #pragma unroll
            for (int pr = 0; pr < 2; pr++) {
                int r  = wn * 32 + pr * 16 + ((lane >> 4) & 1) * 8 + (lane & 7);
                int kq = (2 * ks + ((lane >> 3) & 1)) ^ ((r >> 1) & 3);
                LDMATRIX_X4(b[pr * 2][0], b[pr * 2][1], b[pr * 2 + 1][0], b[pr * 2 + 1][1],
                            sB + (uint32_t)(r * 64 + kq * 16));
            }
            #pragma unroll
            for (int mt = 0; mt < 4; mt++)
                #pragma unroll
                for (int nt = 0; nt < 4; nt++)
                    MMA16816(acc[mt][nt][0], acc[mt][nt][1], acc[mt][nt][2], acc[mt][nt][3],
                             a[mt][0], a[mt][1], a[mt][2], a[mt][3],
                             b[nt][0], b[nt][1]);
        }
        __syncthreads();
    }

    // epilogue
    #pragma unroll
    for (int mt = 0; mt < 4; mt++) {
        int r0 = row0 + wm * 64 + mt * 16 + gq;
        int r1 = r0 + 8;
        #pragma unroll
        for (int nt = 0; nt < 4; nt++) {
            int gc = col0 + wn * 32 + nt * 8 + tq * 2;
            float2 bb = make_float2(0.f, 0.f);
            if (MODE != 1) bb = *reinterpret_cast<const float2*>(&bias[gc]);
            float2 v0 = make_float2(acc[mt][nt][0], acc[mt][nt][1]);
            float2 v1 = make_float2(acc[mt][nt][2], acc[mt][nt][3]);
            if (MODE != 1) { v0.x += bb.x; v0.y += bb.y; v1.x += bb.x; v1.y += bb.y; }
            if (MODE == 0) {
                v0.x = fmaxf(v0.x, 0.f); v0.y = fmaxf(v0.y, 0.f);
                v1.x = fmaxf(v1.x, 0.f); v1.y = fmaxf(v1.y, 0.f);
            }
            if (r0 < M) {
                if (MODE == 0) {
                    unsigned short hx, hy, lx, ly;
                    split2(v0.x, v0.y, hx, hy, lx, ly);
                    *reinterpret_cast<ushort2*>(&Ohi[(size_t)r0 * N + gc]) = make_ushort2(hx, hy);
                    *reinterpret_cast<ushort2*>(&Olo[(size_t)r0 * N + gc]) = make_ushort2(lx, ly);
                } else {
                    *reinterpret_cast<float2*>(&C[(size_t)r0 * N + gc]) = v0;
                }
            }
            if (r1 < M) {
                if (MODE == 0) {
                    unsigned short hx, hy, lx, ly;
                    split2(v1.x, v1.y, hx, hy, lx, ly);
                    *reinterpret_cast<ushort2*>(&Ohi[(size_t)r1 * N + gc]) = make_ushort2(hx, hy);
                    *reinterpret_cast<ushort2*>(&Olo[(size_t)r1 * N + gc]) = make_ushort2(lx, ly);
                } else {
                    *reinterpret_cast<float2*>(&C[(size_t)r1 * N + gc]) = v1;
                }
            }
        }
    }
}

// ---------------------------------------------------------------------------
// CSR aggregation: one warp per node.
//   h[n] = bias + dinv[n]^2*hw[n] + sum_e dinv[src]*dinv[n]*hw[src]
// Output written directly as fp16 hi/lo for the next GEMM.
// ---------------------------------------------------------------------------
__global__ void __launch_bounds__(256)
agg_kernel(const float* __restrict__ hw,
           const int* __restrict__ rowptr, const int* __restrict__ csrsrc,
           const float* __restrict__ dinv, const float* __restrict__ bias,
           __half* __restrict__ ohi, __half* __restrict__ olo) {
    int warp = (blockIdx.x * blockDim.x + threadIdx.x) >> 5;
    if (warp >= N_NODES) return;
    const int lane = threadIdx.x & 31;
    const int n = warp;
    const float di = __ldg(&dinv[n]);
    const float nm = di * di;

    float4 acc[4];
    const float4* self4 = reinterpret_cast<const float4*>(hw + (size_t)n * D_HID);
    const float4* bias4 = reinterpret_cast<const float4*>(bias);
    #pragma unroll
    for (int k = 0; k < 4; k++) {
        float4 b = __ldg(bias4 + lane + 32 * k);
        float4 v = __ldg(self4 + lane + 32 * k);
        acc[k].x = fmaf(v.x, nm, b.x);
        acc[k].y = fmaf(v.y, nm, b.y);
        acc[k].z = fmaf(v.z, nm, b.z);
        acc[k].w = fmaf(v.w, nm, b.w);
    }

    const int e0 = __ldg(&rowptr[n]);
    const int e1 = __ldg(&rowptr[n + 1]);
    for (int e = e0; e < e1; e++) {
        int s = __ldg(&csrsrc[e]);
        float w = __ldg(&dinv[s]) * di;
        const float4* row = reinterpret_cast<const float4*>(hw + (size_t)s * D_HID);
        #pragma unroll
        for (int k = 0; k < 4; k++) {
            float4 v = __ldg(row + lane + 32 * k);
            acc[k].x = fmaf(v.x, w, acc[k].x);
            acc[k].y = fmaf(v.y, w, acc[k].y);
            acc[k].z = fmaf(v.z, w, acc[k].z);
            acc[k].w = fmaf(v.w, w, acc[k].w);
        }
    }

    #pragma unroll
    for (int k = 0; k < 4; k++) {
        size_t base = (size_t)n * D_HID + lane * 4 + 128 * k;
        unsigned short hx, hy, hz, hwv, lx, ly, lz, lw;
        split2(acc[k].x, acc[k].y, hx, hy, lx, ly);
        split2(acc[k].z, acc[k].w, hz, hwv, lz, lw);
        *reinterpret_cast<ushort4*>(ohi + base) = make_ushort4(hx, hy, hz, hwv);
        *reinterpret_cast<ushort4*>(olo + base) = make_ushort4(lx, ly, lz, lw);
    }
}

// ---------------------------------------------------------------------------
extern "C" void kernel_launch(void* const* d_in, const int* in_sizes, int n_in,
                              void* d_out, int out_size) {
    const float* x  = (const float*)d_in[0];
    const int*   ei = (const int*)  d_in[1];
    const float* W1 = (const float*)d_in[2];
    const float* b1 = (const float*)d_in[3];
    const float* Wc = (const float*)d_in[4];
    const float* bc = (const float*)d_in[5];
    const float* W2 = (const float*)d_in[6];
    const float* b2 = (const float*)d_in[7];
    float* out = (float*)d_out;

    float *hw, *dinv;
    __half *ahi, *alo, *bhi, *blo, *whi;
    int *rowcnt, *cursor, *rowptr, *bsum, *csrsrc;
    cudaGetSymbolAddress((void**)&hw,     g_hw);
    cudaGetSymbolAddress((void**)&dinv,   g_dinv);
    cudaGetSymbolAddress((void**)&ahi,    g_ahi);
    cudaGetSymbolAddress((void**)&alo,    g_alo);
    cudaGetSymbolAddress((void**)&bhi,    g_bhi);
    cudaGetSymbolAddress((void**)&blo,    g_blo);
    cudaGetSymbolAddress((void**)&whi,    g_whi);
    cudaGetSymbolAddress((void**)&rowcnt, g_rowcnt);
    cudaGetSymbolAddress((void**)&cursor, g_cursor);
    cudaGetSymbolAddress((void**)&rowptr, g_rowptr);
    cudaGetSymbolAddress((void**)&bsum,   g_bsum);
    cudaGetSymbolAddress((void**)&csrsrc, g_csrsrc);

    const int* srcI = ei;
    const int* dstI = ei + N_EDGES;

    // CSR build + dinv
    hist_zero_kernel<<<(N_NODES + 255) / 256, 256>>>(rowcnt, cursor);
    hist_kernel     <<<(N_EDGES + 255) / 256, 256>>>(dstI, rowcnt);
    scan_local_kernel<<<SCAN_NB, 1024>>>(rowcnt, rowptr, bsum);
    scan_blocks_kernel<<<1, 32>>>(bsum);
    scan_add_kernel <<<(N_NODES + 255) / 256, 256>>>(rowptr, bsum);
    fill_kernel     <<<(N_EDGES + 255) / 256, 256>>>(srcI, dstI, rowptr, cursor, csrsrc);
    dinv_kernel     <<<(N_NODES + 255) / 256, 256>>>(rowcnt, dinv);

    // weights -> transposed fp16
    conv_wT_kernel<<<(D_IN * D_HID + 255) / 256, 256>>>(W1, whi + W1T_OFF, D_IN, D_HID);
    for (int l = 0; l < N_LAYERS; l++)
        conv_wT_kernel<<<(D_HID * D_HID + 255) / 256, 256>>>(
            Wc + (size_t)l * D_HID * D_HID,
            whi + WCT_OFF + (size_t)l * D_HID * D_HID, D_HID, D_HID);
    conv_wT_kernel<<<(D_HID * D_OUT + 255) / 256, 256>>>(W2, whi + W2T_OFF, D_HID, D_OUT);

    const int GRID_M = (N_NODES + 127) / 128;

    // x -> fp16 hi/lo (ahi/alo)
    {
        long long n4 = (long long)N_NODES * D_IN / 4;
        conv_split_kernel<<<(int)((n4 + 255) / 256), 256>>>(x, ahi, alo, n4);
    }

    // dnn1: split(relu(x @ W1 + b1)) -> bhi/blo
    {
        dim3 g(GRID_M, D_HID / 128);
        gemm_mma_kernel<D_IN, 0><<<g, 256>>>(
            ahi, alo, whi + W1T_OFF, b1, nullptr, bhi, blo,
            N_NODES, D_HID);
    }

    const int agg_blocks = (N_NODES * 32 + 255) / 256;
    for (int l = 0; l < N_LAYERS; l++) {
        dim3 g(GRID_M, D_HID / 128);
        gemm_mma_kernel<D_HID, 1><<<g, 256>>>(
            bhi, blo,
            whi + WCT_OFF + (size_t)l * D_HID * D_HID,
            nullptr, hw, nullptr, nullptr,
            N_NODES, D_HID);
        agg_kernel<<<agg_blocks, 256>>>(hw, rowptr, csrsrc, dinv,
                                        bc + (size_t)l * D_HID, bhi, blo);
    }

    // dnn2: out = h @ W2 + b2
    {
        dim3 g(GRID_M, D_OUT / 128);
        gemm_mma_kernel<D_HID, 2><<<g, 256>>>(
            bhi, blo, whi + W2T_OFF, b2, out, nullptr, nullptr,
            N_NODES, D_OUT);
    }
}

// round 9
// speedup vs baseline: 7.9610x; 1.5880x over previous
#include <cuda_runtime.h>
#include <cuda_fp16.h>
#include <cstdint>

#define N_NODES 50000
#define N_EDGES 400000
#define D_IN    256
#define D_HID   512
#define D_OUT   128
#define N_LAYERS 4
#define SCAN_NB 49   // ceil(50000/1024)

// ---------------------------------------------------------------------------
// Scratch (__device__ globals; allocation-free rule)
// ---------------------------------------------------------------------------
__device__ __align__(16) __half g_hw[(size_t)N_NODES * D_HID];   // fp16 now
__device__ float g_dinv[N_NODES];
__device__ __align__(16) __half g_ahi[(size_t)N_NODES * D_HID];  // x split
__device__ __align__(16) __half g_alo[(size_t)N_NODES * D_HID];
__device__ __align__(16) __half g_bhi[(size_t)N_NODES * D_HID];  // h split
__device__ __align__(16) __half g_blo[(size_t)N_NODES * D_HID];
// CSR
__device__ int g_rowcnt[N_NODES];
__device__ int g_cursor[N_NODES];
__device__ int g_rowptr[N_NODES + 1];
__device__ int g_bsum[64];
__device__ int g_csrsrc[N_EDGES];
// transposed weights, fp16: W1T[512,256] | WcT[4][512,512] | W2T[128,512]
#define W1T_OFF 0
#define WCT_OFF (D_HID * D_IN)
#define W2T_OFF (WCT_OFF + N_LAYERS * D_HID * D_HID)
#define W_TOTAL (W2T_OFF + D_OUT * D_HID)
__device__ __align__(16) __half g_whi[W_TOTAL];

// ---------------------------------------------------------------------------
static __device__ __forceinline__ uint32_t smem_u32(const void* p) {
    uint32_t a;
    asm("{ .reg .u64 t; cvta.to.shared.u64 t, %1; cvt.u32.u64 %0, t; }" : "=r"(a) : "l"(p));
    return a;
}

#define CP_ASYNC16(dst, src) \
    asm volatile("cp.async.cg.shared.global [%0], [%1], 16;" :: "r"(dst), "l"(src) : "memory")
#define CP_COMMIT() asm volatile("cp.async.commit_group;" ::: "memory")
#define CP_WAIT1()  asm volatile("cp.async.wait_group 1;"  ::: "memory")

#define LDMATRIX_X4(r0, r1, r2, r3, addr) \
    asm volatile("ldmatrix.sync.aligned.m8n8.x4.shared.b16 {%0,%1,%2,%3}, [%4];" \
                 : "=r"(r0), "=r"(r1), "=r"(r2), "=r"(r3) : "r"(addr))

#define MMA16816(c0, c1, c2, c3, a0, a1, a2, a3, b0, b1) \
    asm volatile("mma.sync.aligned.m16n8k16.row.col.f32.f16.f16.f32 " \
                 "{%0,%1,%2,%3}, {%4,%5,%6,%7}, {%8,%9}, {%0,%1,%2,%3};" \
                 : "+f"(c0), "+f"(c1), "+f"(c2), "+f"(c3) \
                 : "r"(a0), "r"(a1), "r"(a2), "r"(a3), "r"(b0), "r"(b1))

static __device__ __forceinline__ unsigned short hfb(__half h) {
    return *reinterpret_cast<unsigned short*>(&h);
}
static __device__ __forceinline__ void split2(float x, float y, unsigned short& h2x,
                                              unsigned short& h2y, unsigned short& l2x,
                                              unsigned short& l2y) {
    __half hx = __float2half_rn(x), hy = __float2half_rn(y);
    __half lx = __float2half_rn(x - __half2float(hx));
    __half ly = __float2half_rn(y - __half2float(hy));
    h2x = hfb(hx); h2y = hfb(hy); l2x = hfb(lx); l2y = hfb(ly);
}

// ---------------------------------------------------------------------------
// CSR build + dinv
// ---------------------------------------------------------------------------
__global__ void hist_zero_kernel(int* __restrict__ cnt, int* __restrict__ cur) {
    int n = blockIdx.x * blockDim.x + threadIdx.x;
    if (n < N_NODES) { cnt[n] = 0; cur[n] = 0; }
}
__global__ void hist_kernel(const int* __restrict__ dst, int* __restrict__ cnt) {
    int e = blockIdx.x * blockDim.x + threadIdx.x;
    if (e < N_EDGES) atomicAdd(&cnt[dst[e]], 1);
}
__global__ void scan_local_kernel(const int* __restrict__ cnt, int* __restrict__ rptr,
                                  int* __restrict__ bsum) {
    __shared__ int sh[1024];
    int t = threadIdx.x;
    int i = blockIdx.x * 1024 + t;
    int v = (i < N_NODES) ? cnt[i] : 0;
    sh[t] = v;
    __syncthreads();
    #pragma unroll
    for (int off = 1; off < 1024; off <<= 1) {
        int x = 0;
        if (t >= off) x = sh[t - off];
        __syncthreads();
        if (t >= off) sh[t] += x;
        __syncthreads();
    }
    if (i < N_NODES) rptr[i] = sh[t] - v;   // exclusive
    if (t == 1023) bsum[blockIdx.x] = sh[1023];
}
__global__ void scan_blocks_kernel(int* __restrict__ bsum) {
    if (threadIdx.x == 0) {
        int run = 0;
        for (int b = 0; b < SCAN_NB; b++) { int x = bsum[b]; bsum[b] = run; run += x; }
    }
}
__global__ void scan_add_kernel(int* __restrict__ rptr, const int* __restrict__ bsum) {
    int i = blockIdx.x * blockDim.x + threadIdx.x;
    if (i < N_NODES) rptr[i] += bsum[i >> 10];
    if (i == 0) rptr[N_NODES] = N_EDGES;
}
__global__ void fill_kernel(const int* __restrict__ src, const int* __restrict__ dst,
                            const int* __restrict__ rptr, int* __restrict__ cur,
                            int* __restrict__ csrsrc) {
    int e = blockIdx.x * blockDim.x + threadIdx.x;
    if (e >= N_EDGES) return;
    int d = dst[e];
    int pos = rptr[d] + atomicAdd(&cur[d], 1);
    csrsrc[pos] = src[e];
}
__global__ void dinv_kernel(const int* __restrict__ cnt, float* __restrict__ dinv) {
    int n = blockIdx.x * blockDim.x + threadIdx.x;
    if (n < N_NODES) dinv[n] = rsqrtf((float)cnt[n] + 1.0f);
}

// ---------------------------------------------------------------------------
// x fp32 -> fp16 hi/lo
// ---------------------------------------------------------------------------
__global__ void conv_split_kernel(const float* __restrict__ in,
                                  __half* __restrict__ hi,
                                  __half* __restrict__ lo, long long n4) {
    long long i = (long long)blockIdx.x * blockDim.x + threadIdx.x;
    if (i >= n4) return;
    float4 v = reinterpret_cast<const float4*>(in)[i];
    unsigned short hx, hy, hz, hwv, lx, ly, lz, lw;
    split2(v.x, v.y, hx, hy, lx, ly);
    split2(v.z, v.w, hz, hwv, lz, lw);
    reinterpret_cast<ushort4*>(hi)[i] = make_ushort4(hx, hy, hz, hwv);
    reinterpret_cast<ushort4*>(lo)[i] = make_ushort4(lx, ly, lz, lw);
}

// W[K,N] fp32 -> WT fp16 [N,K]
__global__ void conv_wT_kernel(const float* __restrict__ W,
                               __half* __restrict__ hi, int K, int N) {
    int idx = blockIdx.x * blockDim.x + threadIdx.x;
    if (idx >= K * N) return;
    int k = idx / N, n = idx % N;
    hi[(size_t)n * K + k] = __float2half_rn(W[idx]);
}

// ---------------------------------------------------------------------------
// HMMA fp16 GEMM.
// NPASS=2: C = (Ahi + Alo) @ Bhi^T (exact A); NPASS=1: C = Ahi @ Bhi^T.
// MODE 0: dnn1 — bias+relu, write fp16 hi/lo split
// MODE 1: conv — write fp16 C (hw)
// MODE 2: dnn2 — bias, write fp32 C
// ---------------------------------------------------------------------------
#define STAGE_BYTES 16384

template<int KDIM, int MODE, int NPASS>
__global__ void __launch_bounds__(256, 2)
gemm_mma_kernel(const __half* __restrict__ Ahi, const __half* __restrict__ Alo,
                const __half* __restrict__ Bhi,
                const float* __restrict__ bias,
                float* __restrict__ Cf, __half* __restrict__ Ch,
                __half* __restrict__ Ohi, __half* __restrict__ Olo,
                int M, int N) {
    __shared__ __align__(1024) char smem[2 * STAGE_BYTES];
    const uint32_t sbase = smem_u32(smem);

    const int tid  = threadIdx.x;
    const int lane = tid & 31;
    const int wid  = tid >> 5;
    const int wm   = wid >> 2;
    const int wn   = wid & 3;
    const int gq   = lane >> 2;
    const int tq   = lane & 3;
    const int row0 = blockIdx.x * 128;
    const int col0 = blockIdx.y * 128;

    constexpr int NC = (NPASS * KDIM) / 32;

    if (row0 + 127 >= M) {
        for (int f = tid; f < 512; f += 256) {
            int r = f >> 2, kq = f & 3;
            if (row0 + r >= M) {
                uint32_t off = (uint32_t)(r * 64 + ((kq ^ ((r >> 1) & 3)) * 16));
                asm volatile("st.shared.v4.b32 [%0], {%1,%1,%1,%1};" :: "r"(sbase + off), "r"(0u));
                asm volatile("st.shared.v4.b32 [%0], {%1,%1,%1,%1};" :: "r"(sbase + STAGE_BYTES + off), "r"(0u));
            }
        }
        __syncthreads();
    }

    float acc[4][4][4];
    #pragma unroll
    for (int i = 0; i < 4; i++)
        #pragma unroll
        for (int j = 0; j < 4; j++)
            #pragma unroll
            for (int q = 0; q < 4; q++) acc[i][j][q] = 0.0f;

    auto load_stage = [&](int stage, int chunk) {
        const int kp  = chunk * 32;
        const int sec = kp / KDIM;                 // 0: Ahi, 1: Alo
        const int k0  = kp - sec * KDIM;
        const __half* As = sec ? Alo : Ahi;
        const uint32_t sA = sbase + stage * STAGE_BYTES;
        const uint32_t sB = sA + 8192;
        #pragma unroll
        for (int f = tid; f < 512; f += 256) {
            int r = f >> 2, kq = f & 3;
            uint32_t off = (uint32_t)(r * 64 + ((kq ^ ((r >> 1) & 3)) * 16));
            int gr = row0 + r;
            if (gr < M) CP_ASYNC16(sA + off, As + (size_t)gr * KDIM + k0 + kq * 8);
            CP_ASYNC16(sB + off, Bhi + (size_t)(col0 + r) * KDIM + k0 + kq * 8);
        }
    };

    load_stage(0, 0);
    CP_COMMIT();

    for (int c = 0; c < NC; c++) {
        if (c + 1 < NC) load_stage((c + 1) & 1, c + 1);
        CP_COMMIT();
        CP_WAIT1();
        __syncthreads();

        const uint32_t sA = sbase + (c & 1) * STAGE_BYTES;
        const uint32_t sB = sA + 8192;

        #pragma unroll
        for (int ks = 0; ks < 2; ks++) {
            uint32_t a[4][4];
            #pragma unroll
            for (int mt = 0; mt < 4; mt++) {
                int r  = wm * 64 + mt * 16 + (lane & 15);
                int kq = (2 * ks + (lane >> 4)) ^ ((r >> 1) & 3);
                LDMATRIX_X4(a[mt][0], a[mt][1], a[mt][2], a[mt][3],
                            sA + (uint32_t)(r * 64 + kq * 16));
            }
            uint32_t b[4][2];
            #pragma unroll
            for (int pr = 0; pr < 2; pr++) {
                int r  = wn * 32 + pr * 16 + ((lane >> 4) & 1) * 8 + (lane & 7);
                int kq = (2 * ks + ((lane >> 3) & 1)) ^ ((r >> 1) & 3);
                LDMATRIX_X4(b[pr * 2][0], b[pr * 2][1], b[pr * 2 + 1][0], b[pr * 2 + 1][1],
                            sB + (uint32_t)(r * 64 + kq * 16));
            }
            #pragma unroll
            for (int mt = 0; mt < 4; mt++)
                #pragma unroll
                for (int nt = 0; nt < 4; nt++)
                    MMA16816(acc[mt][nt][0], acc[mt][nt][1], acc[mt][nt][2], acc[mt][nt][3],
                             a[mt][0], a[mt][1], a[mt][2], a[mt][3],
                             b[nt][0], b[nt][1]);
        }
        __syncthreads();
    }

    // epilogue
    #pragma unroll
    for (int mt = 0; mt < 4; mt++) {
        int r0 = row0 + wm * 64 + mt * 16 + gq;
        int r1 = r0 + 8;
        #pragma unroll
        for (int nt = 0; nt < 4; nt++) {
            int gc = col0 + wn * 32 + nt * 8 + tq * 2;
            float2 bb = make_float2(0.f, 0.f);
            if (MODE != 1) bb = *reinterpret_cast<const float2*>(&bias[gc]);
            float2 v0 = make_float2(acc[mt][nt][0], acc[mt][nt][1]);
            float2 v1 = make_float2(acc[mt][nt][2], acc[mt][nt][3]);
            if (MODE != 1) { v0.x += bb.x; v0.y += bb.y; v1.x += bb.x; v1.y += bb.y; }
            if (MODE == 0) {
                v0.x = fmaxf(v0.x, 0.f); v0.y = fmaxf(v0.y, 0.f);
                v1.x = fmaxf(v1.x, 0.f); v1.y = fmaxf(v1.y, 0.f);
            }
            if (r0 < M) {
                if (MODE == 0) {
                    unsigned short hx, hy, lx, ly;
                    split2(v0.x, v0.y, hx, hy, lx, ly);
                    *reinterpret_cast<ushort2*>(&Ohi[(size_t)r0 * N + gc]) = make_ushort2(hx, hy);
                    *reinterpret_cast<ushort2*>(&Olo[(size_t)r0 * N + gc]) = make_ushort2(lx, ly);
                } else if (MODE == 1) {
                    *reinterpret_cast<__half2*>(&Ch[(size_t)r0 * N + gc]) =
                        __floats2half2_rn(v0.x, v0.y);
                } else {
                    *reinterpret_cast<float2*>(&Cf[(size_t)r0 * N + gc]) = v0;
                }
            }
            if (r1 < M) {
                if (MODE == 0) {
                    unsigned short hx, hy, lx, ly;
                    split2(v1.x, v1.y, hx, hy, lx, ly);
                    *reinterpret_cast<ushort2*>(&Ohi[(size_t)r1 * N + gc]) = make_ushort2(hx, hy);
                    *reinterpret_cast<ushort2*>(&Olo[(size_t)r1 * N + gc]) = make_ushort2(lx, ly);
                } else if (MODE == 1) {
                    *reinterpret_cast<__half2*>(&Ch[(size_t)r1 * N + gc]) =
                        __floats2half2_rn(v1.x, v1.y);
                } else {
                    *reinterpret_cast<float2*>(&Cf[(size_t)r1 * N + gc]) = v1;
                }
            }
        }
    }
}

// ---------------------------------------------------------------------------
// CSR aggregation: one warp per node, fp16 hw input.
//   h[n] = bias + dinv[n]^2*hw[n] + sum_e dinv[src]*dinv[n]*hw[src]
// fp32 accumulate; output fp16 hi (+lo if WLO).
// ---------------------------------------------------------------------------
template<bool WLO>
__global__ void __launch_bounds__(256)
agg_kernel(const __half* __restrict__ hw,
           const int* __restrict__ rowptr, const int* __restrict__ csrsrc,
           const float* __restrict__ dinv, const float* __restrict__ bias,
           __half* __restrict__ ohi, __half* __restrict__ olo) {
    int warp = (blockIdx.x * blockDim.x + threadIdx.x) >> 5;
    if (warp >= N_NODES) return;
    const int lane = threadIdx.x & 31;
    const int n = warp;
    const float di = __ldg(&dinv[n]);
    const float nm = di * di;

    float acc[16];
    const uint4* self8 = reinterpret_cast<const uint4*>(hw + (size_t)n * D_HID);
    const float4* bias4 = reinterpret_cast<const float4*>(bias);
    #pragma unroll
    for (int k = 0; k < 2; k++) {
        uint4 v = __ldg(self8 + lane + 32 * k);
        const uint32_t vr[4] = {v.x, v.y, v.z, v.w};
        #pragma unroll
        for (int q = 0; q < 4; q++) {
            float2 f = __half22float2(*reinterpret_cast<const __half2*>(&vr[q]));
            float4 b0 = __ldg(bias4 + (lane + 32 * k) * 2 + (q >> 1));
            float bx = (q & 1) ? b0.z : b0.x;
            float by = (q & 1) ? b0.w : b0.y;
            acc[k * 8 + q * 2 + 0] = fmaf(f.x, nm, bx);
            acc[k * 8 + q * 2 + 1] = fmaf(f.y, nm, by);
        }
    }

    const int e0 = __ldg(&rowptr[n]);
    const int e1 = __ldg(&rowptr[n + 1]);
    for (int e = e0; e < e1; e++) {
        int s = __ldg(&csrsrc[e]);
        float w = __ldg(&dinv[s]) * di;
        const uint4* row8 = reinterpret_cast<const uint4*>(hw + (size_t)s * D_HID);
        #pragma unroll
        for (int k = 0; k < 2; k++) {
            uint4 v = __ldg(row8 + lane + 32 * k);
            const uint32_t vr[4] = {v.x, v.y, v.z, v.w};
            #pragma unroll
            for (int q = 0; q < 4; q++) {
                float2 f = __half22float2(*reinterpret_cast<const __half2*>(&vr[q]));
                acc[k * 8 + q * 2 + 0] = fmaf(f.x, w, acc[k * 8 + q * 2 + 0]);
                acc[k * 8 + q * 2 + 1] = fmaf(f.y, w, acc[k * 8 + q * 2 + 1]);
            }
        }
    }

    #pragma unroll
    for (int k = 0; k < 2; k++) {
        size_t base = (size_t)n * D_HID + (lane + 32 * k) * 8;
        unsigned short h[8], l[8];
        #pragma unroll
        for (int q = 0; q < 4; q++)
            split2(acc[k * 8 + q * 2], acc[k * 8 + q * 2 + 1],
                   h[q * 2], h[q * 2 + 1], l[q * 2], l[q * 2 + 1]);
        *reinterpret_cast<ushort4*>(ohi + base)     = make_ushort4(h[0], h[1], h[2], h[3]);
        *reinterpret_cast<ushort4*>(ohi + base + 4) = make_ushort4(h[4], h[5], h[6], h[7]);
        if (WLO) {
            *reinterpret_cast<ushort4*>(olo + base)     = make_ushort4(l[0], l[1], l[2], l[3]);
            *reinterpret_cast<ushort4*>(olo + base + 4) = make_ushort4(l[4], l[5], l[6], l[7]);
        }
    }
}

// ---------------------------------------------------------------------------
extern "C" void kernel_launch(void* const* d_in, const int* in_sizes, int n_in,
                              void* d_out, int out_size) {
    const float* x  = (const float*)d_in[0];
    const int*   ei = (const int*)  d_in[1];
    const float* W1 = (const float*)d_in[2];
    const float* b1 = (const float*)d_in[3];
    const float* Wc = (const float*)d_in[4];
    const float* bc = (const float*)d_in[5];
    const float* W2 = (const float*)d_in[6];
    const float* b2 = (const float*)d_in[7];
    float* out = (float*)d_out;

    float *dinv;
    __half *hw, *ahi, *alo, *bhi, *blo, *whi;
    int *rowcnt, *cursor, *rowptr, *bsum, *csrsrc;
    cudaGetSymbolAddress((void**)&hw,     g_hw);
    cudaGetSymbolAddress((void**)&dinv,   g_dinv);
    cudaGetSymbolAddress((void**)&ahi,    g_ahi);
    cudaGetSymbolAddress((void**)&alo,    g_alo);
    cudaGetSymbolAddress((void**)&bhi,    g_bhi);
    cudaGetSymbolAddress((void**)&blo,    g_blo);
    cudaGetSymbolAddress((void**)&whi,    g_whi);
    cudaGetSymbolAddress((void**)&rowcnt, g_rowcnt);
    cudaGetSymbolAddress((void**)&cursor, g_cursor);
    cudaGetSymbolAddress((void**)&rowptr, g_rowptr);
    cudaGetSymbolAddress((void**)&bsum,   g_bsum);
    cudaGetSymbolAddress((void**)&csrsrc, g_csrsrc);

    const int* srcI = ei;
    const int* dstI = ei + N_EDGES;

    // CSR build + dinv
    hist_zero_kernel<<<(N_NODES + 255) / 256, 256>>>(rowcnt, cursor);
    hist_kernel     <<<(N_EDGES + 255) / 256, 256>>>(dstI, rowcnt);
    scan_local_kernel<<<SCAN_NB, 1024>>>(rowcnt, rowptr, bsum);
    scan_blocks_kernel<<<1, 32>>>(bsum);
    scan_add_kernel <<<(N_NODES + 255) / 256, 256>>>(rowptr, bsum);
    fill_kernel     <<<(N_EDGES + 255) / 256, 256>>>(srcI, dstI, rowptr, cursor, csrsrc);
    dinv_kernel     <<<(N_NODES + 255) / 256, 256>>>(rowcnt, dinv);

    // weights -> transposed fp16
    conv_wT_kernel<<<(D_IN * D_HID + 255) / 256, 256>>>(W1, whi + W1T_OFF, D_IN, D_HID);
    for (int l = 0; l < N_LAYERS; l++)
        conv_wT_kernel<<<(D_HID * D_HID + 255) / 256, 256>>>(
            Wc + (size_t)l * D_HID * D_HID,
            whi + WCT_OFF + (size_t)l * D_HID * D_HID, D_HID, D_HID);
    conv_wT_kernel<<<(D_HID * D_OUT + 255) / 256, 256>>>(W2, whi + W2T_OFF, D_HID, D_OUT);

    const int GRID_M = (N_NODES + 127) / 128;

    // x -> fp16 hi/lo
    {
        long long n4 = (long long)N_NODES * D_IN / 4;
        conv_split_kernel<<<(int)((n4 + 255) / 256), 256>>>(x, ahi, alo, n4);
    }

    // dnn1: split(relu(x @ W1 + b1)) -> bhi/blo  (2-pass exact A)
    {
        dim3 g(GRID_M, D_HID / 128);
        gemm_mma_kernel<D_IN, 0, 2><<<g, 256>>>(
            ahi, alo, whi + W1T_OFF, b1, nullptr, nullptr, bhi, blo,
            N_NODES, D_HID);
    }

    const int agg_blocks = (N_NODES * 32 + 255) / 256;
    for (int l = 0; l < N_LAYERS; l++) {
        // conv GEMM: single-pass (A = bhi only), fp16 hw output
        dim3 g(GRID_M, D_HID / 128);
        gemm_mma_kernel<D_HID, 1, 1><<<g, 256>>>(
            bhi, nullptr,
            whi + WCT_OFF + (size_t)l * D_HID * D_HID,
            nullptr, nullptr, hw, nullptr, nullptr,
            N_NODES, D_HID);
        if (l == N_LAYERS - 1)
            agg_kernel<true><<<agg_blocks, 256>>>(hw, rowptr, csrsrc, dinv,
                                                  bc + (size_t)l * D_HID, bhi, blo);
        else
            agg_kernel<false><<<agg_blocks, 256>>>(hw, rowptr, csrsrc, dinv,
                                                   bc + (size_t)l * D_HID, bhi, nullptr);
    }

    // dnn2: out = h @ W2 + b2  (2-pass exact A)
    {
        dim3 g(GRID_M, D_OUT / 128);
        gemm_mma_kernel<D_HID, 2, 2><<<g, 256>>>(
            bhi, blo, whi + W2T_OFF, b2, out, nullptr, nullptr, nullptr,
            N_NODES, D_OUT);
    }
}

// round 10
// speedup vs baseline: 8.9936x; 1.1297x over previous
#include <cuda_runtime.h>
#include <cuda_fp16.h>
#include <cstdint>

#define N_NODES 50000
#define N_EDGES 400000
#define D_IN    256
#define D_HID   512
#define D_OUT   128
#define N_LAYERS 4
#define SCAN_NB 49   // ceil(50000/1024)

// ---------------------------------------------------------------------------
// Scratch (__device__ globals; allocation-free rule)
// ---------------------------------------------------------------------------
__device__ __align__(16) __half g_hw[(size_t)N_NODES * D_HID];
__device__ float g_dinv[N_NODES];
__device__ __align__(16) __half g_a[(size_t)N_NODES * D_HID];   // x fp16
__device__ __align__(16) __half g_b[(size_t)N_NODES * D_HID];   // h fp16
// CSR
__device__ int g_rowcnt[N_NODES];
__device__ int g_cursor[N_NODES];
__device__ int g_rowptr[N_NODES + 1];
__device__ int g_bsum[64];
__device__ int g_csrsrc[N_EDGES];
// transposed weights, fp16: W1T[512,256] | WcT[4][512,512] | W2T[128,512]
#define W1T_OFF 0
#define WCT_OFF (D_HID * D_IN)
#define W2T_OFF (WCT_OFF + N_LAYERS * D_HID * D_HID)
#define W_TOTAL (W2T_OFF + D_OUT * D_HID)
__device__ __align__(16) __half g_whi[W_TOTAL];

// ---------------------------------------------------------------------------
static __device__ __forceinline__ uint32_t smem_u32(const void* p) {
    uint32_t a;
    asm("{ .reg .u64 t; cvta.to.shared.u64 t, %1; cvt.u32.u64 %0, t; }" : "=r"(a) : "l"(p));
    return a;
}

#define CP_ASYNC16(dst, src) \
    asm volatile("cp.async.cg.shared.global [%0], [%1], 16;" :: "r"(dst), "l"(src) : "memory")
#define CP_COMMIT() asm volatile("cp.async.commit_group;" ::: "memory")
#define CP_WAIT1()  asm volatile("cp.async.wait_group 1;"  ::: "memory")

#define LDMATRIX_X4(r0, r1, r2, r3, addr) \
    asm volatile("ldmatrix.sync.aligned.m8n8.x4.shared.b16 {%0,%1,%2,%3}, [%4];" \
                 : "=r"(r0), "=r"(r1), "=r"(r2), "=r"(r3) : "r"(addr))

#define MMA16816(c0, c1, c2, c3, a0, a1, a2, a3, b0, b1) \
    asm volatile("mma.sync.aligned.m16n8k16.row.col.f32.f16.f16.f32 " \
                 "{%0,%1,%2,%3}, {%4,%5,%6,%7}, {%8,%9}, {%0,%1,%2,%3};" \
                 : "+f"(c0), "+f"(c1), "+f"(c2), "+f"(c3) \
                 : "r"(a0), "r"(a1), "r"(a2), "r"(a3), "r"(b0), "r"(b1))

static __device__ __forceinline__ unsigned short hfb(__half h) {
    return *reinterpret_cast<unsigned short*>(&h);
}

// ---------------------------------------------------------------------------
// CSR build + dinv
// ---------------------------------------------------------------------------
__global__ void hist_zero_kernel(int* __restrict__ cnt, int* __restrict__ cur) {
    int n = blockIdx.x * blockDim.x + threadIdx.x;
    if (n < N_NODES) { cnt[n] = 0; cur[n] = 0; }
}
__global__ void hist_kernel(const int* __restrict__ dst, int* __restrict__ cnt) {
    int e = blockIdx.x * blockDim.x + threadIdx.x;
    if (e < N_EDGES) atomicAdd(&cnt[dst[e]], 1);
}
__global__ void scan_local_kernel(const int* __restrict__ cnt, int* __restrict__ rptr,
                                  int* __restrict__ bsum) {
    __shared__ int sh[1024];
    int t = threadIdx.x;
    int i = blockIdx.x * 1024 + t;
    int v = (i < N_NODES) ? cnt[i] : 0;
    sh[t] = v;
    __syncthreads();
    #pragma unroll
    for (int off = 1; off < 1024; off <<= 1) {
        int x = 0;
        if (t >= off) x = sh[t - off];
        __syncthreads();
        if (t >= off) sh[t] += x;
        __syncthreads();
    }
    if (i < N_NODES) rptr[i] = sh[t] - v;   // exclusive
    if (t == 1023) bsum[blockIdx.x] = sh[1023];
}
__global__ void scan_blocks_kernel(int* __restrict__ bsum) {
    if (threadIdx.x == 0) {
        int run = 0;
        for (int b = 0; b < SCAN_NB; b++) { int x = bsum[b]; bsum[b] = run; run += x; }
    }
}
__global__ void scan_add_kernel(int* __restrict__ rptr, const int* __restrict__ bsum) {
    int i = blockIdx.x * blockDim.x + threadIdx.x;
    if (i < N_NODES) rptr[i] += bsum[i >> 10];
    if (i == 0) rptr[N_NODES] = N_EDGES;
}
__global__ void fill_kernel(const int* __restrict__ src, const int* __restrict__ dst,
                            const int* __restrict__ rptr, int* __restrict__ cur,
                            int* __restrict__ csrsrc) {
    int e = blockIdx.x * blockDim.x + threadIdx.x;
    if (e >= N_EDGES) return;
    int d = dst[e];
    int pos = rptr[d] + atomicAdd(&cur[d], 1);
    csrsrc[pos] = src[e];
}
__global__ void dinv_kernel(const int* __restrict__ cnt, float* __restrict__ dinv) {
    int n = blockIdx.x * blockDim.x + threadIdx.x;
    if (n < N_NODES) dinv[n] = rsqrtf((float)cnt[n] + 1.0f);
}

// ---------------------------------------------------------------------------
// x fp32 -> fp16
// ---------------------------------------------------------------------------
__global__ void conv_x_kernel(const float* __restrict__ in,
                              __half* __restrict__ o, long long n4) {
    long long i = (long long)blockIdx.x * blockDim.x + threadIdx.x;
    if (i >= n4) return;
    float4 v = reinterpret_cast<const float4*>(in)[i];
    __half2 lo = __floats2half2_rn(v.x, v.y);
    __half2 hi = __floats2half2_rn(v.z, v.w);
    reinterpret_cast<uint2*>(o)[i] =
        make_uint2(*reinterpret_cast<uint32_t*>(&lo), *reinterpret_cast<uint32_t*>(&hi));
}

// W[K,N] fp32 -> WT fp16 [N,K]
__global__ void conv_wT_kernel(const float* __restrict__ W,
                               __half* __restrict__ hi, int K, int N) {
    int idx = blockIdx.x * blockDim.x + threadIdx.x;
    if (idx >= K * N) return;
    int k = idx / N, n = idx % N;
    hi[(size_t)n * K + k] = __float2half_rn(W[idx]);
}

// ---------------------------------------------------------------------------
// HMMA fp16 GEMM, single pass: C = A @ B^T.
// MODE 0: dnn1 — bias+relu, write fp16
// MODE 1: conv — write fp16 C (hw)
// MODE 2: dnn2 — bias, write fp32 C
// Block tile 128x128, BK=32, 8 warps, cp.async 2-stage, swizzled ldmatrix.
// ---------------------------------------------------------------------------
#define STAGE_BYTES 16384

template<int KDIM, int MODE>
__global__ void __launch_bounds__(256, 2)
gemm_mma_kernel(const __half* __restrict__ A, const __half* __restrict__ B,
                const float* __restrict__ bias,
                float* __restrict__ Cf, __half* __restrict__ Ch,
                int M, int N) {
    __shared__ __align__(1024) char smem[2 * STAGE_BYTES];
    const uint32_t sbase = smem_u32(smem);

    const int tid  = threadIdx.x;
    const int lane = tid & 31;
    const int wid  = tid >> 5;
    const int wm   = wid >> 2;
    const int wn   = wid & 3;
    const int gq   = lane >> 2;
    const int tq   = lane & 3;
    const int row0 = blockIdx.x * 128;
    const int col0 = blockIdx.y * 128;

    constexpr int NC = KDIM / 32;

    if (row0 + 127 >= M) {
        for (int f = tid; f < 512; f += 256) {
            int r = f >> 2, kq = f & 3;
            if (row0 + r >= M) {
                uint32_t off = (uint32_t)(r * 64 + ((kq ^ ((r >> 1) & 3)) * 16));
                asm volatile("st.shared.v4.b32 [%0], {%1,%1,%1,%1};" :: "r"(sbase + off), "r"(0u));
                asm volatile("st.shared.v4.b32 [%0], {%1,%1,%1,%1};" :: "r"(sbase + STAGE_BYTES + off), "r"(0u));
            }
        }
        __syncthreads();
    }

    float acc[4][4][4];
    #pragma unroll
    for (int i = 0; i < 4; i++)
        #pragma unroll
        for (int j = 0; j < 4; j++)
            #pragma unroll
            for (int q = 0; q < 4; q++) acc[i][j][q] = 0.0f;

    auto load_stage = [&](int stage, int chunk) {
        const int k0 = chunk * 32;
        const uint32_t sA = sbase + stage * STAGE_BYTES;
        const uint32_t sB = sA + 8192;
        #pragma unroll
        for (int f = tid; f < 512; f += 256) {
            int r = f >> 2, kq = f & 3;
            uint32_t off = (uint32_t)(r * 64 + ((kq ^ ((r >> 1) & 3)) * 16));
            int gr = row0 + r;
            if (gr < M) CP_ASYNC16(sA + off, A + (size_t)gr * KDIM + k0 + kq * 8);
            CP_ASYNC16(sB + off, B + (size_t)(col0 + r) * KDIM + k0 + kq * 8);
        }
    };

    load_stage(0, 0);
    CP_COMMIT();

    for (int c = 0; c < NC; c++) {
        if (c + 1 < NC) load_stage((c + 1) & 1, c + 1);
        CP_COMMIT();
        CP_WAIT1();
        __syncthreads();

        const uint32_t sA = sbase + (c & 1) * STAGE_BYTES;
        const uint32_t sB = sA + 8192;

        #pragma unroll
        for (int ks = 0; ks < 2; ks++) {
            uint32_t a[4][4];
            #pragma unroll
            for (int mt = 0; mt < 4; mt++) {
                int r  = wm * 64 + mt * 16 + (lane & 15);
                int kq = (2 * ks + (lane >> 4)) ^ ((r >> 1) & 3);
                LDMATRIX_X4(a[mt][0], a[mt][1], a[mt][2], a[mt][3],
                            sA + (uint32_t)(r * 64 + kq * 16));
            }
            uint32_t b[4][2];
            #pragma unroll
            for (int pr = 0; pr < 2; pr++) {
                int r  = wn * 32 + pr * 16 + ((lane >> 4) & 1) * 8 + (lane & 7);
                int kq = (2 * ks + ((lane >> 3) & 1)) ^ ((r >> 1) & 3);
                LDMATRIX_X4(b[pr * 2][0], b[pr * 2][1], b[pr * 2 + 1][0], b[pr * 2 + 1][1],
                            sB + (uint32_t)(r * 64 + kq * 16));
            }
            #pragma unroll
            for (int mt = 0; mt < 4; mt++)
                #pragma unroll
                for (int nt = 0; nt < 4; nt++)
                    MMA16816(acc[mt][nt][0], acc[mt][nt][1], acc[mt][nt][2], acc[mt][nt][3],
                             a[mt][0], a[mt][1], a[mt][2], a[mt][3],
                             b[nt][0], b[nt][1]);
        }
        __syncthreads();
    }

    // epilogue
    #pragma unroll
    for (int mt = 0; mt < 4; mt++) {
        int r0 = row0 + wm * 64 + mt * 16 + gq;
        int r1 = r0 + 8;
        #pragma unroll
        for (int nt = 0; nt < 4; nt++) {
            int gc = col0 + wn * 32 + nt * 8 + tq * 2;
            float2 bb = make_float2(0.f, 0.f);
            if (MODE != 1) bb = *reinterpret_cast<const float2*>(&bias[gc]);
            float2 v0 = make_float2(acc[mt][nt][0], acc[mt][nt][1]);
            float2 v1 = make_float2(acc[mt][nt][2], acc[mt][nt][3]);
            if (MODE != 1) { v0.x += bb.x; v0.y += bb.y; v1.x += bb.x; v1.y += bb.y; }
            if (MODE == 0) {
                v0.x = fmaxf(v0.x, 0.f); v0.y = fmaxf(v0.y, 0.f);
                v1.x = fmaxf(v1.x, 0.f); v1.y = fmaxf(v1.y, 0.f);
            }
            if (r0 < M) {
                if (MODE == 2) {
                    *reinterpret_cast<float2*>(&Cf[(size_t)r0 * N + gc]) = v0;
                } else {
                    *reinterpret_cast<__half2*>(&Ch[(size_t)r0 * N + gc]) =
                        __floats2half2_rn(v0.x, v0.y);
                }
            }
            if (r1 < M) {
                if (MODE == 2) {
                    *reinterpret_cast<float2*>(&Cf[(size_t)r1 * N + gc]) = v1;
                } else {
                    *reinterpret_cast<__half2*>(&Ch[(size_t)r1 * N + gc]) =
                        __floats2half2_rn(v1.x, v1.y);
                }
            }
        }
    }
}

// ---------------------------------------------------------------------------
// CSR aggregation: one warp per node, fp16 hw input, fp32 accum, fp16 out.
//   h[n] = bias + dinv[n]^2*hw[n] + sum_e dinv[src]*dinv[n]*hw[src]
// ---------------------------------------------------------------------------
__global__ void __launch_bounds__(256)
agg_kernel(const __half* __restrict__ hw,
           const int* __restrict__ rowptr, const int* __restrict__ csrsrc,
           const float* __restrict__ dinv, const float* __restrict__ bias,
           __half* __restrict__ oh) {
    int warp = (blockIdx.x * blockDim.x + threadIdx.x) >> 5;
    if (warp >= N_NODES) return;
    const int lane = threadIdx.x & 31;
    const int n = warp;
    const float di = __ldg(&dinv[n]);
    const float nm = di * di;

    float acc[16];
    const uint4* self8 = reinterpret_cast<const uint4*>(hw + (size_t)n * D_HID);
    const float4* bias4 = reinterpret_cast<const float4*>(bias);
    #pragma unroll
    for (int k = 0; k < 2; k++) {
        uint4 v = __ldg(self8 + lane + 32 * k);
        const uint32_t vr[4] = {v.x, v.y, v.z, v.w};
        #pragma unroll
        for (int q = 0; q < 4; q++) {
            float2 f = __half22float2(*reinterpret_cast<const __half2*>(&vr[q]));
            float4 b0 = __ldg(bias4 + (lane + 32 * k) * 2 + (q >> 1));
            float bx = (q & 1) ? b0.z : b0.x;
            float by = (q & 1) ? b0.w : b0.y;
            acc[k * 8 + q * 2 + 0] = fmaf(f.x, nm, bx);
            acc[k * 8 + q * 2 + 1] = fmaf(f.y, nm, by);
        }
    }

    const int e0 = __ldg(&rowptr[n]);
    const int e1 = __ldg(&rowptr[n + 1]);
    for (int e = e0; e < e1; e++) {
        int s = __ldg(&csrsrc[e]);
        float w = __ldg(&dinv[s]) * di;
        const uint4* row8 = reinterpret_cast<const uint4*>(hw + (size_t)s * D_HID);
        #pragma unroll
        for (int k = 0; k < 2; k++) {
            uint4 v = __ldg(row8 + lane + 32 * k);
            const uint32_t vr[4] = {v.x, v.y, v.z, v.w};
            #pragma unroll
            for (int q = 0; q < 4; q++) {
                float2 f = __half22float2(*reinterpret_cast<const __half2*>(&vr[q]));
                acc[k * 8 + q * 2 + 0] = fmaf(f.x, w, acc[k * 8 + q * 2 + 0]);
                acc[k * 8 + q * 2 + 1] = fmaf(f.y, w, acc[k * 8 + q * 2 + 1]);
            }
        }
    }

    #pragma unroll
    for (int k = 0; k < 2; k++) {
        size_t base = (size_t)n * D_HID + (lane + 32 * k) * 8;
        uint32_t h[4];
        #pragma unroll
        for (int q = 0; q < 4; q++) {
            __half2 p = __floats2half2_rn(acc[k * 8 + q * 2], acc[k * 8 + q * 2 + 1]);
            h[q] = *reinterpret_cast<uint32_t*>(&p);
        }
        *reinterpret_cast<uint4*>(oh + base) = make_uint4(h[0], h[1], h[2], h[3]);
    }
}

// ---------------------------------------------------------------------------
extern "C" void kernel_launch(void* const* d_in, const int* in_sizes, int n_in,
                              void* d_out, int out_size) {
    const float* x  = (const float*)d_in[0];
    const int*   ei = (const int*)  d_in[1];
    const float* W1 = (const float*)d_in[2];
    const float* b1 = (const float*)d_in[3];
    const float* Wc = (const float*)d_in[4];
    const float* bc = (const float*)d_in[5];
    const float* W2 = (const float*)d_in[6];
    const float* b2 = (const float*)d_in[7];
    float* out = (float*)d_out;

    float *dinv;
    __half *hw, *a, *b, *whi;
    int *rowcnt, *cursor, *rowptr, *bsum, *csrsrc;
    cudaGetSymbolAddress((void**)&hw,     g_hw);
    cudaGetSymbolAddress((void**)&dinv,   g_dinv);
    cudaGetSymbolAddress((void**)&a,      g_a);
    cudaGetSymbolAddress((void**)&b,      g_b);
    cudaGetSymbolAddress((void**)&whi,    g_whi);
    cudaGetSymbolAddress((void**)&rowcnt, g_rowcnt);
    cudaGetSymbolAddress((void**)&cursor, g_cursor);
    cudaGetSymbolAddress((void**)&rowptr, g_rowptr);
    cudaGetSymbolAddress((void**)&bsum,   g_bsum);
    cudaGetSymbolAddress((void**)&csrsrc, g_csrsrc);

    const int* srcI = ei;
    const int* dstI = ei + N_EDGES;

    // CSR build + dinv
    hist_zero_kernel<<<(N_NODES + 255) / 256, 256>>>(rowcnt, cursor);
    hist_kernel     <<<(N_EDGES + 255) / 256, 256>>>(dstI, rowcnt);
    scan_local_kernel<<<SCAN_NB, 1024>>>(rowcnt, rowptr, bsum);
    scan_blocks_kernel<<<1, 32>>>(bsum);
    scan_add_kernel <<<(N_NODES + 255) / 256, 256>>>(rowptr, bsum);
    fill_kernel     <<<(N_EDGES + 255) / 256, 256>>>(srcI, dstI, rowptr, cursor, csrsrc);
    dinv_kernel     <<<(N_NODES + 255) / 256, 256>>>(rowcnt, dinv);

    // weights -> transposed fp16
    conv_wT_kernel<<<(D_IN * D_HID + 255) / 256, 256>>>(W1, whi + W1T_OFF, D_IN, D_HID);
    for (int l = 0; l < N_LAYERS; l++)
        conv_wT_kernel<<<(D_HID * D_HID + 255) / 256, 256>>>(
            Wc + (size_t)l * D_HID * D_HID,
            whi + WCT_OFF + (size_t)l * D_HID * D_HID, D_HID, D_HID);
    conv_wT_kernel<<<(D_HID * D_OUT + 255) / 256, 256>>>(W2, whi + W2T_OFF, D_HID, D_OUT);

    const int GRID_M = (N_NODES + 127) / 128;

    // x -> fp16
    {
        long long n4 = (long long)N_NODES * D_IN / 4;
        conv_x_kernel<<<(int)((n4 + 255) / 256), 256>>>(x, a, n4);
    }

    // dnn1: fp16(relu(x @ W1 + b1)) -> b
    {
        dim3 g(GRID_M, D_HID / 128);
        gemm_mma_kernel<D_IN, 0><<<g, 256>>>(
            a, whi + W1T_OFF, b1, nullptr, b, N_NODES, D_HID);
    }

    const int agg_blocks = (N_NODES * 32 + 255) / 256;
    for (int l = 0; l < N_LAYERS; l++) {
        dim3 g(GRID_M, D_HID / 128);
        gemm_mma_kernel<D_HID, 1><<<g, 256>>>(
            b, whi + WCT_OFF + (size_t)l * D_HID * D_HID,
            nullptr, nullptr, hw, N_NODES, D_HID);
        agg_kernel<<<agg_blocks, 256>>>(hw, rowptr, csrsrc, dinv,
                                        bc + (size_t)l * D_HID, b);
    }

    // dnn2: out = h @ W2 + b2
    {
        dim3 g(GRID_M, D_OUT / 128);
        gemm_mma_kernel<D_HID, 2><<<g, 256>>>(
            b, whi + W2T_OFF, b2, out, nullptr, N_NODES, D_OUT);
    }
}

// round 11
// speedup vs baseline: 9.3764x; 1.0426x over previous
#include <cuda_runtime.h>
#include <cuda_fp16.h>
#include <cstdint>

#define N_NODES 50000
#define N_EDGES 400000
#define D_IN    256
#define D_HID   512
#define D_OUT   128
#define N_LAYERS 4
#define SCAN_NB 49   // ceil(50000/1024)

// ---------------------------------------------------------------------------
// Scratch (__device__ globals; allocation-free rule)
// ---------------------------------------------------------------------------
__device__ __align__(16) __half g_hw[(size_t)N_NODES * D_HID];
__device__ float g_dinv[N_NODES];
__device__ __align__(16) __half g_a[(size_t)N_NODES * D_HID];   // x fp16
__device__ __align__(16) __half g_b[(size_t)N_NODES * D_HID];   // h fp16
// CSR
__device__ int g_rowcnt[N_NODES];
__device__ int g_cursor[N_NODES];
__device__ int g_rowptr[N_NODES + 1];
__device__ int g_bsum[64];
__device__ int g_csrsrc[N_EDGES];
// transposed weights, fp16: W1T[512,256] | WcT[4][512,512] | W2T[128,512]
#define W1T_OFF 0
#define WCT_OFF (D_HID * D_IN)
#define W2T_OFF (WCT_OFF + N_LAYERS * D_HID * D_HID)
#define W_TOTAL (W2T_OFF + D_OUT * D_HID)
__device__ __align__(16) __half g_whi[W_TOTAL];

// ---------------------------------------------------------------------------
static __device__ __forceinline__ uint32_t smem_u32(const void* p) {
    uint32_t a;
    asm("{ .reg .u64 t; cvta.to.shared.u64 t, %1; cvt.u32.u64 %0, t; }" : "=r"(a) : "l"(p));
    return a;
}

#define CP_ASYNC16(dst, src) \
    asm volatile("cp.async.cg.shared.global [%0], [%1], 16;" :: "r"(dst), "l"(src) : "memory")
#define CP_COMMIT() asm volatile("cp.async.commit_group;" ::: "memory")
#define CP_WAIT1()  asm volatile("cp.async.wait_group 1;"  ::: "memory")

#define LDMATRIX_X4(r0, r1, r2, r3, addr) \
    asm volatile("ldmatrix.sync.aligned.m8n8.x4.shared.b16 {%0,%1,%2,%3}, [%4];" \
                 : "=r"(r0), "=r"(r1), "=r"(r2), "=r"(r3) : "r"(addr))

#define MMA16816(c0, c1, c2, c3, a0, a1, a2, a3, b0, b1) \
    asm volatile("mma.sync.aligned.m16n8k16.row.col.f32.f16.f16.f32 " \
                 "{%0,%1,%2,%3}, {%4,%5,%6,%7}, {%8,%9}, {%0,%1,%2,%3};" \
                 : "+f"(c0), "+f"(c1), "+f"(c2), "+f"(c3) \
                 : "r"(a0), "r"(a1), "r"(a2), "r"(a3), "r"(b0), "r"(b1))

// ---------------------------------------------------------------------------
// CSR build + dinv
// ---------------------------------------------------------------------------
__global__ void hist_zero_kernel(int* __restrict__ cnt, int* __restrict__ cur) {
    int n = blockIdx.x * blockDim.x + threadIdx.x;
    if (n < N_NODES) { cnt[n] = 0; cur[n] = 0; }
}
__global__ void hist_kernel(const int* __restrict__ dst, int* __restrict__ cnt) {
    int e = blockIdx.x * blockDim.x + threadIdx.x;
    if (e < N_EDGES) atomicAdd(&cnt[dst[e]], 1);
}
__global__ void scan_local_kernel(const int* __restrict__ cnt, int* __restrict__ rptr,
                                  int* __restrict__ bsum) {
    __shared__ int sh[1024];
    int t = threadIdx.x;
    int i = blockIdx.x * 1024 + t;
    int v = (i < N_NODES) ? cnt[i] : 0;
    sh[t] = v;
    __syncthreads();
    #pragma unroll
    for (int off = 1; off < 1024; off <<= 1) {
        int x = 0;
        if (t >= off) x = sh[t - off];
        __syncthreads();
        if (t >= off) sh[t] += x;
        __syncthreads();
    }
    if (i < N_NODES) rptr[i] = sh[t] - v;   // exclusive
    if (t == 1023) bsum[blockIdx.x] = sh[1023];
}
__global__ void scan_blocks_kernel(int* __restrict__ bsum) {
    if (threadIdx.x == 0) {
        int run = 0;
        for (int b = 0; b < SCAN_NB; b++) { int x = bsum[b]; bsum[b] = run; run += x; }
    }
}
__global__ void scan_add_kernel(int* __restrict__ rptr, const int* __restrict__ bsum) {
    int i = blockIdx.x * blockDim.x + threadIdx.x;
    if (i < N_NODES) rptr[i] += bsum[i >> 10];
    if (i == 0) rptr[N_NODES] = N_EDGES;
}
__global__ void fill_kernel(const int* __restrict__ src, const int* __restrict__ dst,
                            const int* __restrict__ rptr, int* __restrict__ cur,
                            int* __restrict__ csrsrc) {
    int e = blockIdx.x * blockDim.x + threadIdx.x;
    if (e >= N_EDGES) return;
    int d = dst[e];
    int pos = rptr[d] + atomicAdd(&cur[d], 1);
    csrsrc[pos] = src[e];
}
__global__ void dinv_kernel(const int* __restrict__ cnt, float* __restrict__ dinv) {
    int n = blockIdx.x * blockDim.x + threadIdx.x;
    if (n < N_NODES) dinv[n] = rsqrtf((float)cnt[n] + 1.0f);
}

// ---------------------------------------------------------------------------
// x fp32 -> fp16
// ---------------------------------------------------------------------------
__global__ void conv_x_kernel(const float* __restrict__ in,
                              __half* __restrict__ o, long long n4) {
    long long i = (long long)blockIdx.x * blockDim.x + threadIdx.x;
    if (i >= n4) return;
    float4 v = reinterpret_cast<const float4*>(in)[i];
    __half2 lo = __floats2half2_rn(v.x, v.y);
    __half2 hi = __floats2half2_rn(v.z, v.w);
    reinterpret_cast<uint2*>(o)[i] =
        make_uint2(*reinterpret_cast<uint32_t*>(&lo), *reinterpret_cast<uint32_t*>(&hi));
}

// W[K,N] fp32 -> WT fp16 [N,K]
__global__ void conv_wT_kernel(const float* __restrict__ W,
                               __half* __restrict__ hi, int K, int N) {
    int idx = blockIdx.x * blockDim.x + threadIdx.x;
    if (idx >= K * N) return;
    int k = idx / N, n = idx % N;
    hi[(size_t)n * K + k] = __float2half_rn(W[idx]);
}

// ---------------------------------------------------------------------------
// HMMA fp16 GEMM, single pass: C = A @ B^T, 3-stage cp.async pipeline.
// MODE 0: dnn1 — bias+relu, write fp16
// MODE 1: conv — write fp16 C (hw)
// MODE 2: dnn2 — bias, write fp32 C
// Block tile 128x128, BK=32, 8 warps, swizzled ldmatrix.
// ---------------------------------------------------------------------------
#define STAGE_BYTES 16384
#define NSTAGE 3

template<int KDIM, int MODE>
__global__ void __launch_bounds__(256, 2)
gemm_mma_kernel(const __half* __restrict__ A, const __half* __restrict__ B,
                const float* __restrict__ bias,
                float* __restrict__ Cf, __half* __restrict__ Ch,
                int M, int N) {
    __shared__ __align__(1024) char smem[NSTAGE * STAGE_BYTES];
    const uint32_t sbase = smem_u32(smem);

    const int tid  = threadIdx.x;
    const int lane = tid & 31;
    const int wid  = tid >> 5;
    const int wm   = wid >> 2;
    const int wn   = wid & 3;
    const int gq   = lane >> 2;
    const int tq   = lane & 3;
    const int row0 = blockIdx.x * 128;
    const int col0 = blockIdx.y * 128;

    constexpr int NC = KDIM / 32;

    if (row0 + 127 >= M) {
        for (int f = tid; f < 512; f += 256) {
            int r = f >> 2, kq = f & 3;
            if (row0 + r >= M) {
                uint32_t off = (uint32_t)(r * 64 + ((kq ^ ((r >> 1) & 3)) * 16));
                #pragma unroll
                for (int s = 0; s < NSTAGE; s++)
                    asm volatile("st.shared.v4.b32 [%0], {%1,%1,%1,%1};"
                                 :: "r"(sbase + s * STAGE_BYTES + off), "r"(0u));
            }
        }
        __syncthreads();
    }

    float acc[4][4][4];
    #pragma unroll
    for (int i = 0; i < 4; i++)
        #pragma unroll
        for (int j = 0; j < 4; j++)
            #pragma unroll
            for (int q = 0; q < 4; q++) acc[i][j][q] = 0.0f;

    auto load_stage = [&](int stage, int chunk) {
        const int k0 = chunk * 32;
        const uint32_t sA = sbase + stage * STAGE_BYTES;
        const uint32_t sB = sA + 8192;
        #pragma unroll
        for (int f = tid; f < 512; f += 256) {
            int r = f >> 2, kq = f & 3;
            uint32_t off = (uint32_t)(r * 64 + ((kq ^ ((r >> 1) & 3)) * 16));
            int gr = row0 + r;
            if (gr < M) CP_ASYNC16(sA + off, A + (size_t)gr * KDIM + k0 + kq * 8);
            CP_ASYNC16(sB + off, B + (size_t)(col0 + r) * KDIM + k0 + kq * 8);
        }
    };

    load_stage(0, 0);
    CP_COMMIT();
    if (NC > 1) { load_stage(1, 1); CP_COMMIT(); }

    int stage = 0;
    for (int c = 0; c < NC; c++) {
        CP_WAIT1();          // stage for chunk c complete (≤1 group pending)
        __syncthreads();

        const uint32_t sA = sbase + stage * STAGE_BYTES;
        const uint32_t sB = sA + 8192;

        #pragma unroll
        for (int ks = 0; ks < 2; ks++) {
            uint32_t a[4][4];
            #pragma unroll
            for (int mt = 0; mt < 4; mt++) {
                int r  = wm * 64 + mt * 16 + (lane & 15);
                int kq = (2 * ks + (lane >> 4)) ^ ((r >> 1) & 3);
                LDMATRIX_X4(a[mt][0], a[mt][1], a[mt][2], a[mt][3],
                            sA + (uint32_t)(r * 64 + kq * 16));
            }
            uint32_t b[4][2];
            #pragma unroll
            for (int pr = 0; pr < 2; pr++) {
                int r  = wn * 32 + pr * 16 + ((lane >> 4) & 1) * 8 + (lane & 7);
                int kq = (2 * ks + ((lane >> 3) & 1)) ^ ((r >> 1) & 3);
                LDMATRIX_X4(b[pr * 2][0], b[pr * 2][1], b[pr * 2 + 1][0], b[pr * 2 + 1][1],
                            sB + (uint32_t)(r * 64 + kq * 16));
            }
            #pragma unroll
            for (int mt = 0; mt < 4; mt++)
                #pragma unroll
                for (int nt = 0; nt < 4; nt++)
                    MMA16816(acc[mt][nt][0], acc[mt][nt][1], acc[mt][nt][2], acc[mt][nt][3],
                             a[mt][0], a[mt][1], a[mt][2], a[mt][3],
                             b[nt][0], b[nt][1]);
        }
        __syncthreads();     // stage consumed; safe to overwrite

        if (c + 2 < NC) {
            int ns = stage;  // reuse the just-freed stage? no: rotate
            ns = (stage + 2) % NSTAGE;
            load_stage(ns, c + 2);
            CP_COMMIT();
        }
        stage = (stage + 1) % NSTAGE;
    }

    // epilogue
    #pragma unroll
    for (int mt = 0; mt < 4; mt++) {
        int r0 = row0 + wm * 64 + mt * 16 + gq;
        int r1 = r0 + 8;
        #pragma unroll
        for (int nt = 0; nt < 4; nt++) {
            int gc = col0 + wn * 32 + nt * 8 + tq * 2;
            float2 bb = make_float2(0.f, 0.f);
            if (MODE != 1) bb = *reinterpret_cast<const float2*>(&bias[gc]);
            float2 v0 = make_float2(acc[mt][nt][0], acc[mt][nt][1]);
            float2 v1 = make_float2(acc[mt][nt][2], acc[mt][nt][3]);
            if (MODE != 1) { v0.x += bb.x; v0.y += bb.y; v1.x += bb.x; v1.y += bb.y; }
            if (MODE == 0) {
                v0.x = fmaxf(v0.x, 0.f); v0.y = fmaxf(v0.y, 0.f);
                v1.x = fmaxf(v1.x, 0.f); v1.y = fmaxf(v1.y, 0.f);
            }
            if (r0 < M) {
                if (MODE == 2) {
                    *reinterpret_cast<float2*>(&Cf[(size_t)r0 * N + gc]) = v0;
                } else {
                    *reinterpret_cast<__half2*>(&Ch[(size_t)r0 * N + gc]) =
                        __floats2half2_rn(v0.x, v0.y);
                }
            }
            if (r1 < M) {
                if (MODE == 2) {
                    *reinterpret_cast<float2*>(&Cf[(size_t)r1 * N + gc]) = v1;
                } else {
                    *reinterpret_cast<__half2*>(&Ch[(size_t)r1 * N + gc]) =
                        __floats2half2_rn(v1.x, v1.y);
                }
            }
        }
    }
}

// ---------------------------------------------------------------------------
// CSR aggregation: one warp per node, fp16 hw, fp32 accum, fp16 out.
// Edge loop unrolled x2 for memory-level parallelism.
// ---------------------------------------------------------------------------
__global__ void __launch_bounds__(256)
agg_kernel(const __half* __restrict__ hw,
           const int* __restrict__ rowptr, const int* __restrict__ csrsrc,
           const float* __restrict__ dinv, const float* __restrict__ bias,
           __half* __restrict__ oh) {
    int warp = (blockIdx.x * blockDim.x + threadIdx.x) >> 5;
    if (warp >= N_NODES) return;
    const int lane = threadIdx.x & 31;
    const int n = warp;
    const float di = __ldg(&dinv[n]);
    const float nm = di * di;

    float acc[16];
    const uint4* self8 = reinterpret_cast<const uint4*>(hw + (size_t)n * D_HID);
    const float4* bias4 = reinterpret_cast<const float4*>(bias);
    #pragma unroll
    for (int k = 0; k < 2; k++) {
        uint4 v = __ldg(self8 + lane + 32 * k);
        const uint32_t vr[4] = {v.x, v.y, v.z, v.w};
        #pragma unroll
        for (int q = 0; q < 4; q++) {
            float2 f = __half22float2(*reinterpret_cast<const __half2*>(&vr[q]));
            float4 b0 = __ldg(bias4 + (lane + 32 * k) * 2 + (q >> 1));
            float bx = (q & 1) ? b0.z : b0.x;
            float by = (q & 1) ? b0.w : b0.y;
            acc[k * 8 + q * 2 + 0] = fmaf(f.x, nm, bx);
            acc[k * 8 + q * 2 + 1] = fmaf(f.y, nm, by);
        }
    }

    const int e0 = __ldg(&rowptr[n]);
    const int e1 = __ldg(&rowptr[n + 1]);
    int e = e0;
    for (; e + 2 <= e1; e += 2) {
        int s0 = __ldg(&csrsrc[e]);
        int s1 = __ldg(&csrsrc[e + 1]);
        float w0 = __ldg(&dinv[s0]) * di;
        float w1 = __ldg(&dinv[s1]) * di;
        const uint4* r0 = reinterpret_cast<const uint4*>(hw + (size_t)s0 * D_HID);
        const uint4* r1 = reinterpret_cast<const uint4*>(hw + (size_t)s1 * D_HID);
        uint4 v00 = __ldg(r0 + lane);
        uint4 v01 = __ldg(r0 + lane + 32);
        uint4 v10 = __ldg(r1 + lane);
        uint4 v11 = __ldg(r1 + lane + 32);
        const uint4 vv[4] = {v00, v01, v10, v11};
        const float ww[4] = {w0, w0, w1, w1};
        #pragma unroll
        for (int p = 0; p < 4; p++) {
            int k = p & 1;
            const uint32_t vr[4] = {vv[p].x, vv[p].y, vv[p].z, vv[p].w};
            #pragma unroll
            for (int q = 0; q < 4; q++) {
                float2 f = __half22float2(*reinterpret_cast<const __half2*>(&vr[q]));
                acc[k * 8 + q * 2 + 0] = fmaf(f.x, ww[p], acc[k * 8 + q * 2 + 0]);
                acc[k * 8 + q * 2 + 1] = fmaf(f.y, ww[p], acc[k * 8 + q * 2 + 1]);
            }
        }
    }
    for (; e < e1; e++) {
        int s = __ldg(&csrsrc[e]);
        float w = __ldg(&dinv[s]) * di;
        const uint4* row8 = reinterpret_cast<const uint4*>(hw + (size_t)s * D_HID);
        #pragma unroll
        for (int k = 0; k < 2; k++) {
            uint4 v = __ldg(row8 + lane + 32 * k);
            const uint32_t vr[4] = {v.x, v.y, v.z, v.w};
            #pragma unroll
            for (int q = 0; q < 4; q++) {
                float2 f = __half22float2(*reinterpret_cast<const __half2*>(&vr[q]));
                acc[k * 8 + q * 2 + 0] = fmaf(f.x, w, acc[k * 8 + q * 2 + 0]);
                acc[k * 8 + q * 2 + 1] = fmaf(f.y, w, acc[k * 8 + q * 2 + 1]);
            }
        }
    }

    #pragma unroll
    for (int k = 0; k < 2; k++) {
        size_t base = (size_t)n * D_HID + (lane + 32 * k) * 8;
        uint32_t h[4];
        #pragma unroll
        for (int q = 0; q < 4; q++) {
            __half2 p = __floats2half2_rn(acc[k * 8 + q * 2], acc[k * 8 + q * 2 + 1]);
            h[q] = *reinterpret_cast<uint32_t*>(&p);
        }
        *reinterpret_cast<uint4*>(oh + base) = make_uint4(h[0], h[1], h[2], h[3]);
    }
}

// ---------------------------------------------------------------------------
extern "C" void kernel_launch(void* const* d_in, const int* in_sizes, int n_in,
                              void* d_out, int out_size) {
    const float* x  = (const float*)d_in[0];
    const int*   ei = (const int*)  d_in[1];
    const float* W1 = (const float*)d_in[2];
    const float* b1 = (const float*)d_in[3];
    const float* Wc = (const float*)d_in[4];
    const float* bc = (const float*)d_in[5];
    const float* W2 = (const float*)d_in[6];
    const float* b2 = (const float*)d_in[7];
    float* out = (float*)d_out;

    float *dinv;
    __half *hw, *a, *b, *whi;
    int *rowcnt, *cursor, *rowptr, *bsum, *csrsrc;
    cudaGetSymbolAddress((void**)&hw,     g_hw);
    cudaGetSymbolAddress((void**)&dinv,   g_dinv);
    cudaGetSymbolAddress((void**)&a,      g_a);
    cudaGetSymbolAddress((void**)&b,      g_b);
    cudaGetSymbolAddress((void**)&whi,    g_whi);
    cudaGetSymbolAddress((void**)&rowcnt, g_rowcnt);
    cudaGetSymbolAddress((void**)&cursor, g_cursor);
    cudaGetSymbolAddress((void**)&rowptr, g_rowptr);
    cudaGetSymbolAddress((void**)&bsum,   g_bsum);
    cudaGetSymbolAddress((void**)&csrsrc, g_csrsrc);

    const int* srcI = ei;
    const int* dstI = ei + N_EDGES;

    // CSR build + dinv
    hist_zero_kernel<<<(N_NODES + 255) / 256, 256>>>(rowcnt, cursor);
    hist_kernel     <<<(N_EDGES + 255) / 256, 256>>>(dstI, rowcnt);
    scan_local_kernel<<<SCAN_NB, 1024>>>(rowcnt, rowptr, bsum);
    scan_blocks_kernel<<<1, 32>>>(bsum);
    scan_add_kernel <<<(N_NODES + 255) / 256, 256>>>(rowptr, bsum);
    fill_kernel     <<<(N_EDGES + 255) / 256, 256>>>(srcI, dstI, rowptr, cursor, csrsrc);
    dinv_kernel     <<<(N_NODES + 255) / 256, 256>>>(rowcnt, dinv);

    // weights -> transposed fp16
    conv_wT_kernel<<<(D_IN * D_HID + 255) / 256, 256>>>(W1, whi + W1T_OFF, D_IN, D_HID);
    for (int l = 0; l < N_LAYERS; l++)
        conv_wT_kernel<<<(D_HID * D_HID + 255) / 256, 256>>>(
            Wc + (size_t)l * D_HID * D_HID,
            whi + WCT_OFF + (size_t)l * D_HID * D_HID, D_HID, D_HID);
    conv_wT_kernel<<<(D_HID * D_OUT + 255) / 256, 256>>>(W2, whi + W2T_OFF, D_HID, D_OUT);

    const int GRID_M = (N_NODES + 127) / 128;

    // x -> fp16
    {
        long long n4 = (long long)N_NODES * D_IN / 4;
        conv_x_kernel<<<(int)((n4 + 255) / 256), 256>>>(x, a, n4);
    }

    // dnn1: fp16(relu(x @ W1 + b1)) -> b
    {
        dim3 g(GRID_M, D_HID / 128);
        gemm_mma_kernel<D_IN, 0><<<g, 256>>>(
            a, whi + W1T_OFF, b1, nullptr, b, N_NODES, D_HID);
    }

    const int agg_blocks = (N_NODES * 32 + 255) / 256;
    for (int l = 0; l < N_LAYERS; l++) {
        dim3 g(GRID_M, D_HID / 128);
        gemm_mma_kernel<D_HID, 1><<<g, 256>>>(
            b, whi + WCT_OFF + (size_t)l * D_HID * D_HID,
            nullptr, nullptr, hw, N_NODES, D_HID);
        agg_kernel<<<agg_blocks, 256>>>(hw, rowptr, csrsrc, dinv,
                                        bc + (size_t)l * D_HID, b);
    }

    // dnn2: out = h @ W2 + b2
    {
        dim3 g(GRID_M, D_OUT / 128);
        gemm_mma_kernel<D_HID, 2><<<g, 256>>>(
            b, whi + W2T_OFF, b2, out, nullptr, N_NODES, D_OUT);
    }
}